// round 14
// baseline (speedup 1.0000x reference)
#include <cuda_runtime.h>
#include <cuda_bf16.h>
#include <math.h>
#include <stdint.h>

// Problem constants
#define NB    4
#define CIN   1024
#define CINT  512
#define HH    96
#define WW    96
#define PP    (HH * WW)      // 9216
#define DD    4
#define QQ    81
#define CSPLIT 2             // corr channel split
#define ASPLIT 8             // assemble channel split

// ---------------------------------------------------------------------------
// Scratch (device globals; no allocation allowed)
// ---------------------------------------------------------------------------
__device__ __align__(128) __nv_bfloat16 g_xb   [NB * CIN  * PP];
__device__ __align__(128) __nv_bfloat16 g_xrefb[NB * CIN  * PP];
__device__ __align__(128) __nv_bfloat16 g_wb   [4 * CINT * CIN];   // theta,g,phi,out
__device__ __align__(128) float g_theta [NB * CINT * PP];
__device__ __align__(128) float g_g     [NB * CINT * PP];
__device__ __align__(128) float g_phi   [NB * CINT * PP];
__device__ __align__(128) float g_pwpart[CSPLIT * NB * QQ * PP];
__device__ __align__(128) float g_pw    [NB * QQ * PP];
__device__ __align__(128) __nv_bfloat16 g_yb   [NB * CINT * PP];

// ---------------------------------------------------------------------------
// Helpers (legacy path: cp.async + ldmatrix + mma.sync; no tcgen05 — the
// toolchain targets sm_103 without the 'a' feature set)
// ---------------------------------------------------------------------------
__device__ __forceinline__ uint32_t sptr(const void* p) {
    return (uint32_t)__cvta_generic_to_shared(p);
}
__device__ __forceinline__ void cp16(uint32_t dst, const void* src) {
    asm volatile("cp.async.cg.shared.global [%0], [%1], 16;" :: "r"(dst), "l"(src));
}
__device__ __forceinline__ void cp_commit() {
    asm volatile("cp.async.commit_group;");
}
__device__ __forceinline__ void cp_wait0() {
    asm volatile("cp.async.wait_group 0;");
}
__device__ __forceinline__ void cp_wait1() {
    asm volatile("cp.async.wait_group 1;");
}
__device__ __forceinline__ void cp_wait2() {
    asm volatile("cp.async.wait_group 2;");
}
__device__ __forceinline__ void ldsmx4(uint32_t* r, uint32_t addr) {
    asm volatile("ldmatrix.sync.aligned.m8n8.x4.shared.b16 {%0,%1,%2,%3}, [%4];"
                 : "=r"(r[0]), "=r"(r[1]), "=r"(r[2]), "=r"(r[3]) : "r"(addr));
}
__device__ __forceinline__ void ldsmx4t(uint32_t* r, uint32_t addr) {
    asm volatile("ldmatrix.sync.aligned.m8n8.x4.trans.shared.b16 {%0,%1,%2,%3}, [%4];"
                 : "=r"(r[0]), "=r"(r[1]), "=r"(r[2]), "=r"(r[3]) : "r"(addr));
}
__device__ __forceinline__ void mma16816(float* c, const uint32_t* a, const uint32_t* b) {
    asm volatile("mma.sync.aligned.m16n8k16.row.col.f32.bf16.bf16.f32 "
                 "{%0,%1,%2,%3}, {%4,%5,%6,%7}, {%8,%9}, {%0,%1,%2,%3};"
                 : "+f"(c[0]), "+f"(c[1]), "+f"(c[2]), "+f"(c[3])
                 : "r"(a[0]), "r"(a[1]), "r"(a[2]), "r"(a[3]), "r"(b[0]), "r"(b[1]));
}

// ---------------------------------------------------------------------------
// Merged conversions: activations (z: 0=x, 1=x_ref) and weights (z: 0..3)
// ---------------------------------------------------------------------------
__global__ void __launch_bounds__(256)
convx_kernel(const float* __restrict__ x, const float* __restrict__ xref,
             __nv_bfloat16* __restrict__ xb, __nv_bfloat16* __restrict__ xrefb)
{
    const float* in = blockIdx.z ? xref : x;
    __nv_bfloat16* out = blockIdx.z ? xrefb : xb;
    int i = (blockIdx.x * 256 + threadIdx.x) * 8;
    float4 v0 = *(const float4*)(in + i);
    float4 v1 = *(const float4*)(in + i + 4);
    __nv_bfloat162 o[4];
    o[0] = __floats2bfloat162_rn(v0.x, v0.y);
    o[1] = __floats2bfloat162_rn(v0.z, v0.w);
    o[2] = __floats2bfloat162_rn(v1.x, v1.y);
    o[3] = __floats2bfloat162_rn(v1.z, v1.w);
    *(uint4*)(out + i) = *(const uint4*)o;
}

__global__ void __launch_bounds__(256)
convw_kernel(const float* __restrict__ w0, const float* __restrict__ w1,
             const float* __restrict__ w2, const float* __restrict__ w3,
             __nv_bfloat16* __restrict__ out)
{
    const int z = blockIdx.z;
    const float* in = (z == 0) ? w0 : (z == 1) ? w1 : (z == 2) ? w2 : w3;
    __nv_bfloat16* o = out + (size_t)z * (CINT * CIN);
    int i = (blockIdx.x * 256 + threadIdx.x) * 8;
    float4 v0 = *(const float4*)(in + i);
    float4 v1 = *(const float4*)(in + i + 4);
    __nv_bfloat162 p[4];
    p[0] = __floats2bfloat162_rn(v0.x, v0.y);
    p[1] = __floats2bfloat162_rn(v0.z, v0.w);
    p[2] = __floats2bfloat162_rn(v1.x, v1.y);
    p[3] = __floats2bfloat162_rn(v1.z, v1.w);
    *(uint4*)(o + i) = *(const uint4*)p;
}

// ---------------------------------------------------------------------------
// bf16 tensor-core GEMM (mma.sync), BK=32, 4-stage cp.async pipeline
// (prefetch distance 3 -> every tile gets 3 compute phases of slack),
// ONE barrier per k-tile. 8 warps (2m x 4n), warp tile 64x32.
// Dynamic smem: 4 * (10240 + 8704) = 75776 B; 2 CTAs/SM.
// ---------------------------------------------------------------------------
#define AS_STRIDE 40
#define BS_STRIDE 136
#define AS_ELEMS (128 * AS_STRIDE)
#define BS_ELEMS (32 * BS_STRIDE)
#define AS_BYTES (AS_ELEMS * 2)      // 10240
#define BS_BYTES (BS_ELEMS * 2)      // 8704
#define GEMM_STAGES 4
#define GEMM_SMEM (GEMM_STAGES * (AS_BYTES + BS_BYTES))   // 75776

__global__ void __launch_bounds__(256, 2)
bgemm_kernel(const __nv_bfloat16* __restrict__ W, const __nv_bfloat16* __restrict__ Z,
             const float* __restrict__ bias, const float* __restrict__ res,
             float* __restrict__ O, int M, int K, int P)
{
    extern __shared__ __align__(16) char dsm[];

    const int b  = blockIdx.z;
    const __nv_bfloat16* Zb = Z + (size_t)b * K * P;
    float*       Ob = O + (size_t)b * M * P;
    const float* Rb = res ? res + (size_t)b * M * P : nullptr;

    const int m0 = blockIdx.y * 128;
    const int n0 = blockIdx.x * 128;
    const int tid  = threadIdx.x;
    const int lane = tid & 31;
    const int wid  = tid >> 5;
    const int wm = wid & 1;
    const int wn = wid >> 1;

    const uint32_t smem0 = sptr(dsm);
    const uint32_t bbase0 = smem0 + GEMM_STAGES * AS_BYTES;

    const int a_r = tid >> 2;
    const int a_c = tid & 3;
    const int b_r = tid >> 4;
    const int b_c = tid & 15;

    float acc[4][4][4];
#pragma unroll
    for (int mt = 0; mt < 4; mt++)
#pragma unroll
        for (int nt = 0; nt < 4; nt++)
#pragma unroll
            for (int i = 0; i < 4; i++) acc[mt][nt][i] = 0.f;

    const int nk = K >> 5;   // 32-wide tiles (nk = 32 or 16; always > 3)

    // prologue: issue tiles 0, 1, 2
#pragma unroll
    for (int pt = 0; pt < 3; pt++) {
        const uint32_t as = smem0 + pt * AS_BYTES;
        const uint32_t bs = bbase0 + pt * BS_BYTES;
        const int k0 = pt * 32;
        cp16(as + (uint32_t)((a_r)      * AS_STRIDE + a_c * 8) * 2, W  + (size_t)(m0 + a_r)      * K + k0 + a_c * 8);
        cp16(as + (uint32_t)((a_r + 64) * AS_STRIDE + a_c * 8) * 2, W  + (size_t)(m0 + a_r + 64) * K + k0 + a_c * 8);
        cp16(bs + (uint32_t)((b_r)      * BS_STRIDE + b_c * 8) * 2, Zb + (size_t)(k0 + b_r)      * P + n0 + b_c * 8);
        cp16(bs + (uint32_t)((b_r + 16) * BS_STRIDE + b_c * 8) * 2, Zb + (size_t)(k0 + b_r + 16) * P + n0 + b_c * 8);
        cp_commit();
    }

    int s = 0;   // stage of tile kt
    for (int kt = 0; kt < nk; kt++) {
        // pending groups: tiles kt..kt+2 (minus completed). Tile kt must be done.
        if (kt + 2 < nk) cp_wait2();
        else if (kt + 1 < nk) cp_wait1();
        else cp_wait0();
        __syncthreads();

        if (kt + 3 < nk) {
            const int sp = (s + 3) & 3;     // stage of tile kt-1, computed last iter
            const uint32_t as = smem0 + sp * AS_BYTES;
            const uint32_t bs = bbase0 + sp * BS_BYTES;
            const int k0 = (kt + 3) * 32;
            cp16(as + (uint32_t)((a_r)      * AS_STRIDE + a_c * 8) * 2, W  + (size_t)(m0 + a_r)      * K + k0 + a_c * 8);
            cp16(as + (uint32_t)((a_r + 64) * AS_STRIDE + a_c * 8) * 2, W  + (size_t)(m0 + a_r + 64) * K + k0 + a_c * 8);
            cp16(bs + (uint32_t)((b_r)      * BS_STRIDE + b_c * 8) * 2, Zb + (size_t)(k0 + b_r)      * P + n0 + b_c * 8);
            cp16(bs + (uint32_t)((b_r + 16) * BS_STRIDE + b_c * 8) * 2, Zb + (size_t)(k0 + b_r + 16) * P + n0 + b_c * 8);
            cp_commit();
        }

        const uint32_t as = smem0 + s * AS_BYTES;
        const uint32_t bs = bbase0 + s * BS_BYTES;

#pragma unroll
        for (int kk = 0; kk < 2; kk++) {
            const int k0 = kk * 16;
            uint32_t a[4][4];
            const uint32_t a_base = as + (uint32_t)(((wm * 64 + (lane & 15)) * AS_STRIDE) + k0 + (lane >> 4) * 8) * 2;
#pragma unroll
            for (int mt = 0; mt < 4; mt++)
                ldsmx4(a[mt], a_base + (uint32_t)(mt * 16 * AS_STRIDE) * 2);

            uint32_t bb[4][2];
            const uint32_t b_base = bs + (uint32_t)((k0 + (lane & 15)) * BS_STRIDE + wn * 32 + (lane >> 4) * 8) * 2;
            {
                uint32_t r[4];
                ldsmx4t(r, b_base);
                bb[0][0] = r[0]; bb[0][1] = r[1];
                bb[1][0] = r[2]; bb[1][1] = r[3];
                ldsmx4t(r, b_base + 16 * 2);
                bb[2][0] = r[0]; bb[2][1] = r[1];
                bb[3][0] = r[2]; bb[3][1] = r[3];
            }

#pragma unroll
            for (int mt = 0; mt < 4; mt++)
#pragma unroll
                for (int nt = 0; nt < 4; nt++)
                    mma16816(acc[mt][nt], a[mt], bb[nt]);
        }
        s = (s + 1) & 3;
    }

#pragma unroll
    for (int mt = 0; mt < 4; mt++) {
        const int r0 = m0 + wm * 64 + mt * 16 + (lane >> 2);
        const int r1 = r0 + 8;
        const float bv0 = bias[r0];
        const float bv1 = bias[r1];
#pragma unroll
        for (int nt = 0; nt < 4; nt++) {
            const int col = n0 + wn * 32 + nt * 8 + (lane & 3) * 2;
            float2 v0 = make_float2(acc[mt][nt][0] + bv0, acc[mt][nt][1] + bv0);
            float2 v1 = make_float2(acc[mt][nt][2] + bv1, acc[mt][nt][3] + bv1);
            if (Rb) {
                float2 t0 = *(const float2*)&Rb[(size_t)r0 * P + col];
                float2 t1 = *(const float2*)&Rb[(size_t)r1 * P + col];
                v0.x += t0.x; v0.y += t0.y;
                v1.x += t1.x; v1.y += t1.y;
            }
            *(float2*)&Ob[(size_t)r0 * P + col] = v0;
            *(float2*)&Ob[(size_t)r1 * P + col] = v1;
        }
    }
}

// ---------------------------------------------------------------------------
// Correlation, 2-pixel y-blocking + register-prefetch pipeline (CCH=4).
// ---------------------------------------------------------------------------
#define CTW 32
#define CTH2 16
#define CWW (CTW + 2 * DD)    // 40
#define CWH (CTH2 + 2 * DD)   // 24
#define CCH 4
#define CPB (CINT / CSPLIT)   // 256
#define TH_F4 ((CCH * CTH2 * CTW) / 4)   // 512 float4
#define PH_F4 ((CCH * CWH * CWW) / 4)    // 960 float4

__global__ void __launch_bounds__(256, 1)
corr_kernel(const float* __restrict__ theta,
            const float* __restrict__ phi,
            float* __restrict__ pwpart)
{
    __shared__ __align__(16) float th_s[CCH * CTH2 * CTW];   // 8 KB
    __shared__ __align__(16) float ph_s[CCH * CWH * CWW];    // 15 KB

    const int z  = blockIdx.z;
    const int b  = z >> 1;
    const int ci = z & 1;
    const int ch0 = ci * CPB;
    const int w0 = blockIdx.x * CTW;
    const int h0 = blockIdx.y * CTH2;
    const int tid = threadIdx.x;
    const int tx = tid & 31;
    const int ty = tid >> 5;          // 0..7 -> pixel rows 2ty, 2ty+1

    const float* thb = theta + (size_t)b * CINT * PP;
    const float* phb = phi   + (size_t)b * CINT * PP;

    float accA[QQ], accB[QQ];
#pragma unroll
    for (int q = 0; q < QQ; q++) { accA[q] = 0.f; accB[q] = 0.f; }

    float4 thr[2];
    float4 phr[4];

#define CORR_LOAD(c0)                                                          \
    {                                                                          \
        _Pragma("unroll")                                                      \
        for (int j = 0; j < 2; j++) {                                          \
            const int idx4 = tid * 2 + j;                                      \
            const int cc  = idx4 >> 7;                                         \
            const int rem = idx4 & 127;                                        \
            const int r   = rem >> 3;                                          \
            const int cg  = rem & 7;                                           \
            thr[j] = *(const float4*)&thb[(size_t)((c0) + cc) * PP +           \
                                          (h0 + r) * WW + w0 + cg * 4];        \
        }                                                                      \
        _Pragma("unroll")                                                      \
        for (int j = 0; j < 4; j++) {                                          \
            const int t = tid + j * 256;                                       \
            if (t < PH_F4) {                                                   \
                const int cc  = t / 240;                                       \
                const int rem = t - cc * 240;                                  \
                const int r   = rem / 10;                                      \
                const int cg  = rem - r * 10;                                  \
                const int hh   = h0 - DD + r;                                  \
                const int gcol = w0 - DD + cg * 4;                             \
                float4 v = make_float4(0.f, 0.f, 0.f, 0.f);                    \
                if (hh >= 0 && hh < HH && gcol >= 0 && gcol < WW)              \
                    v = *(const float4*)&phb[(size_t)((c0) + cc) * PP +        \
                                             hh * WW + gcol];                  \
                phr[j] = v;                                                    \
            }                                                                  \
        }                                                                      \
    }

    CORR_LOAD(ch0);

    const int nch = CPB / CCH;   // 64 chunks
    for (int c = 0; c < nch; c++) {
#pragma unroll
        for (int j = 0; j < 2; j++) ((float4*)th_s)[tid * 2 + j] = thr[j];
#pragma unroll
        for (int j = 0; j < 4; j++) {
            const int t = tid + j * 256;
            if (t < PH_F4) ((float4*)ph_s)[t] = phr[j];
        }
        __syncthreads();

        if (c + 1 < nch) CORR_LOAD(ch0 + (c + 1) * CCH);

#pragma unroll
        for (int cc = 0; cc < CCH; cc++) {
            const float t0 = th_s[cc * (CTH2 * CTW) + (2 * ty)     * CTW + tx];
            const float t1 = th_s[cc * (CTH2 * CTW) + (2 * ty + 1) * CTW + tx];
            const float* pr = &ph_s[cc * (CWH * CWW)];
#pragma unroll
            for (int rr = 0; rr < 10; rr++) {
                const float* row = &pr[(2 * ty + rr) * CWW + tx];
#pragma unroll
                for (int dx = 0; dx < 9; dx++) {
                    const float v = row[dx];
                    if (rr < 9) accA[rr * 9 + dx] += t0 * v;
                    if (rr >= 1) accB[(rr - 1) * 9 + dx] += t1 * v;
                }
            }
        }
        __syncthreads();
    }
#undef CORR_LOAD

    const int pixA = (h0 + 2 * ty) * WW + (w0 + tx);
    float* bp = pwpart + ((size_t)(ci * NB + b) * QQ) * PP;
#pragma unroll
    for (int q = 0; q < QQ; q++) {
        bp[(size_t)q * PP + pixA]      = accA[q];
        bp[(size_t)q * PP + pixA + WW] = accB[q];
    }
}

// ---------------------------------------------------------------------------
// Softmax over Q (sums the 2 channel-split partials, applies scale)
// ---------------------------------------------------------------------------
__global__ void __launch_bounds__(128)
softmax_kernel(const float* __restrict__ part, float* __restrict__ pw)
{
    const int t = blockIdx.x * 128 + threadIdx.x;
    const int b = t / PP;
    const int pix = t - b * PP;
    const size_t qp = (size_t)QQ * PP;
    const float scale = 256.0f / sqrtf((float)WW) / (float)CINT;

    float v[QQ];
    float m = -1e30f;
#pragma unroll
    for (int q = 0; q < QQ; q++) {
        const size_t off = (size_t)q * PP + pix;
        float s = part[(size_t)(0 * NB + b) * qp + off]
                + part[(size_t)(1 * NB + b) * qp + off];
        v[q] = s * scale;
        m = fmaxf(m, v[q]);
    }
    float s = 0.f;
#pragma unroll
    for (int q = 0; q < QQ; q++) { v[q] = __expf(v[q] - m); s += v[q]; }
    const float inv = 1.0f / s;
    float* pwb = pw + (size_t)b * qp + pix;
#pragma unroll
    for (int q = 0; q < QQ; q++) pwb[(size_t)q * PP] = v[q] * inv;
}

// ---------------------------------------------------------------------------
// Assemble, 2-pixel y-blocking + register-prefetch pipeline (CCH=4).
// ---------------------------------------------------------------------------
__global__ void __launch_bounds__(256, 1)
assemble_kernel(const float* __restrict__ pw,
                const float* __restrict__ g,
                __nv_bfloat16* __restrict__ y)
{
    __shared__ __align__(16) float gs[CCH * CWH * CWW];   // 15 KB

    const int z  = blockIdx.z;
    const int b  = z >> 3;
    const int c0base = (z & 7) * (CINT / ASPLIT); // 64 channels
    const int w0 = blockIdx.x * CTW;
    const int h0 = blockIdx.y * CTH2;
    const int tid = threadIdx.x;
    const int tx = tid & 31;
    const int ty = tid >> 5;

    const float* gb  = g  + (size_t)b * CINT * PP;
    const float* pwb = pw + (size_t)b * QQ * PP;
    __nv_bfloat16* yb = y + (size_t)b * CINT * PP;

    const int pixA = (h0 + 2 * ty) * WW + (w0 + tx);
    const int pixB = pixA + WW;

    float rpwA[QQ], rpwB[QQ];
#pragma unroll
    for (int q = 0; q < QQ; q++) {
        rpwA[q] = pwb[(size_t)q * PP + pixA];
        rpwB[q] = pwb[(size_t)q * PP + pixB];
    }

    float4 gr4[4];

#define ASM_LOAD(c0)                                                           \
    {                                                                          \
        _Pragma("unroll")                                                      \
        for (int j = 0; j < 4; j++) {                                          \
            const int t = tid + j * 256;                                       \
            if (t < PH_F4) {                                                   \
                const int cc  = t / 240;                                       \
                const int rem = t - cc * 240;                                  \
                const int r   = rem / 10;                                      \
                const int cg  = rem - r * 10;                                  \
                const int hh   = h0 - DD + r;                                  \
                const int gcol = w0 - DD + cg * 4;                             \
                float4 v = make_float4(0.f, 0.f, 0.f, 0.f);                    \
                if (hh >= 0 && hh < HH && gcol >= 0 && gcol < WW)              \
                    v = *(const float4*)&gb[(size_t)((c0) + cc) * PP +         \
                                            hh * WW + gcol];                   \
                gr4[j] = v;                                                    \
            }                                                                  \
        }                                                                      \
    }

    ASM_LOAD(c0base);

    const int nch = (CINT / ASPLIT) / CCH;   // 16 chunks
    for (int c = 0; c < nch; c++) {
#pragma unroll
        for (int j = 0; j < 4; j++) {
            const int t = tid + j * 256;
            if (t < PH_F4) ((float4*)gs)[t] = gr4[j];
        }
        __syncthreads();

        if (c + 1 < nch) ASM_LOAD(c0base + (c + 1) * CCH);

        const int c0 = c0base + c * CCH;
#pragma unroll
        for (int cc = 0; cc < CCH; cc++) {
            const float* grp = &gs[cc * (CWH * CWW)];
            float aA = 0.f, aB = 0.f;
#pragma unroll
            for (int rr = 0; rr < 10; rr++) {
                const float* row = &grp[(2 * ty + rr) * CWW + tx];
#pragma unroll
                for (int dx = 0; dx < 9; dx++) {
                    const float v = row[dx];
                    if (rr < 9) aA += rpwA[rr * 9 + dx] * v;
                    if (rr >= 1) aB += rpwB[(rr - 1) * 9 + dx] * v;
                }
            }
            yb[(size_t)(c0 + cc) * PP + pixA] = __float2bfloat16(aA);
            yb[(size_t)(c0 + cc) * PP + pixB] = __float2bfloat16(aB);
        }
        __syncthreads();
    }
#undef ASM_LOAD
}

// ---------------------------------------------------------------------------
// Launch
// ---------------------------------------------------------------------------
extern "C" void kernel_launch(void* const* d_in, const int* in_sizes, int n_in,
                              void* d_out, int out_size)
{
    (void)in_sizes; (void)n_in; (void)out_size;

    const float* x       = (const float*)d_in[0];
    const float* x_ref   = (const float*)d_in[1];
    const float* w_g     = (const float*)d_in[2];
    const float* b_g     = (const float*)d_in[3];
    const float* w_theta = (const float*)d_in[4];
    const float* b_theta = (const float*)d_in[5];
    const float* w_phi   = (const float*)d_in[6];
    const float* b_phi   = (const float*)d_in[7];
    const float* w_out   = (const float*)d_in[8];
    const float* b_out   = (const float*)d_in[9];
    float* out = (float*)d_out;

    __nv_bfloat16 *xb, *xrefb, *wb, *yb;
    float *theta, *gbuf, *phi, *pwpart, *pw;
    cudaGetSymbolAddress((void**)&xb,     g_xb);
    cudaGetSymbolAddress((void**)&xrefb,  g_xrefb);
    cudaGetSymbolAddress((void**)&wb,     g_wb);
    cudaGetSymbolAddress((void**)&theta,  g_theta);
    cudaGetSymbolAddress((void**)&gbuf,   g_g);
    cudaGetSymbolAddress((void**)&phi,    g_phi);
    cudaGetSymbolAddress((void**)&pwpart, g_pwpart);
    cudaGetSymbolAddress((void**)&pw,     g_pw);
    cudaGetSymbolAddress((void**)&yb,     g_yb);

    cudaFuncSetAttribute(bgemm_kernel, cudaFuncAttributeMaxDynamicSharedMemorySize, GEMM_SMEM);

    const int WSZ = CINT * CIN;
    __nv_bfloat16* wtb = wb + 0 * WSZ;
    __nv_bfloat16* wgb = wb + 1 * WSZ;
    __nv_bfloat16* wpb = wb + 2 * WSZ;
    __nv_bfloat16* wob = wb + 3 * WSZ;

    // conversions (2 launches)
    const int nx = NB * CIN * PP;
    dim3 cxg(nx / (256 * 8), 1, 2);
    convx_kernel<<<cxg, 256>>>(x, x_ref, xb, xrefb);
    dim3 cwg(WSZ / (256 * 8), 1, 4);
    convw_kernel<<<cwg, 256>>>(w_theta, w_g, w_phi, w_out, wb);

    // 1x1 convs (tensor-core GEMMs, BK=32, 4-stage pipeline)
    dim3 blk(256);
    dim3 gg1(PP / 128, CINT / 128, NB);     // (72, 4, 4)
    bgemm_kernel<<<gg1, blk, GEMM_SMEM>>>(wtb, xb,    b_theta, nullptr, theta, CINT, CIN, PP);
    bgemm_kernel<<<gg1, blk, GEMM_SMEM>>>(wgb, xrefb, b_g,     nullptr, gbuf,  CINT, CIN, PP);
    bgemm_kernel<<<gg1, blk, GEMM_SMEM>>>(wpb, xrefb, b_phi,   nullptr, phi,   CINT, CIN, PP);

    // correlation partials + softmax
    dim3 cg(WW / CTW, HH / CTH2, NB * CSPLIT);   // (3, 6, 8) = 144 blocks
    corr_kernel<<<cg, blk>>>(theta, phi, pwpart);
    softmax_kernel<<<(NB * PP) / 128, 128>>>(pwpart, pw);

    // assemble (bf16 output)
    dim3 ag(WW / CTW, HH / CTH2, NB * ASPLIT);   // (3, 6, 32) = 576 blocks
    assemble_kernel<<<ag, blk>>>(pw, gbuf, yb);

    // final conv + residual
    dim3 gg2(PP / 128, CIN / 128, NB);           // (72, 8, 4)
    bgemm_kernel<<<gg2, blk, GEMM_SMEM>>>(wob, yb, b_out, x, out, CIN, CINT, PP);
}

// round 15
// speedup vs baseline: 1.3863x; 1.3863x over previous
#include <cuda_runtime.h>
#include <cuda_bf16.h>
#include <math.h>
#include <stdint.h>

// Problem constants
#define NB    4
#define CIN   1024
#define CINT  512
#define HH    96
#define WW    96
#define PP    (HH * WW)      // 9216
#define DD    4
#define QQ    81
#define CSPLIT 2             // corr channel split
#define ASPLIT 8             // assemble channel split

// ---------------------------------------------------------------------------
// Scratch (device globals; no allocation allowed)
// ---------------------------------------------------------------------------
__device__ __align__(128) __nv_bfloat16 g_xb   [NB * CIN  * PP];
__device__ __align__(128) __nv_bfloat16 g_xrefb[NB * CIN  * PP];
__device__ __align__(128) __nv_bfloat16 g_wb   [4 * CINT * CIN];   // theta,g,phi,out
__device__ __align__(128) __nv_bfloat16 g_theta[NB * CINT * PP];   // bf16 intermediates
__device__ __align__(128) __nv_bfloat16 g_g    [NB * CINT * PP];
__device__ __align__(128) __nv_bfloat16 g_phi  [NB * CINT * PP];
__device__ __align__(128) float g_pwpart[CSPLIT * NB * QQ * PP];
__device__ __align__(128) float g_pw    [NB * QQ * PP];
__device__ __align__(128) __nv_bfloat16 g_yb   [NB * CINT * PP];

// ---------------------------------------------------------------------------
// Helpers (legacy path: cp.async + ldmatrix + mma.sync; no tcgen05 — the
// toolchain targets sm_103 without the 'a' feature set)
// ---------------------------------------------------------------------------
__device__ __forceinline__ uint32_t sptr(const void* p) {
    return (uint32_t)__cvta_generic_to_shared(p);
}
__device__ __forceinline__ void cp16(uint32_t dst, const void* src) {
    asm volatile("cp.async.cg.shared.global [%0], [%1], 16;" :: "r"(dst), "l"(src));
}
__device__ __forceinline__ void cp_commit() {
    asm volatile("cp.async.commit_group;");
}
__device__ __forceinline__ void cp_wait0() {
    asm volatile("cp.async.wait_group 0;");
}
__device__ __forceinline__ void cp_wait1() {
    asm volatile("cp.async.wait_group 1;");
}
__device__ __forceinline__ void ldsmx4(uint32_t* r, uint32_t addr) {
    asm volatile("ldmatrix.sync.aligned.m8n8.x4.shared.b16 {%0,%1,%2,%3}, [%4];"
                 : "=r"(r[0]), "=r"(r[1]), "=r"(r[2]), "=r"(r[3]) : "r"(addr));
}
__device__ __forceinline__ void ldsmx4t(uint32_t* r, uint32_t addr) {
    asm volatile("ldmatrix.sync.aligned.m8n8.x4.trans.shared.b16 {%0,%1,%2,%3}, [%4];"
                 : "=r"(r[0]), "=r"(r[1]), "=r"(r[2]), "=r"(r[3]) : "r"(addr));
}
__device__ __forceinline__ void mma16816(float* c, const uint32_t* a, const uint32_t* b) {
    asm volatile("mma.sync.aligned.m16n8k16.row.col.f32.bf16.bf16.f32 "
                 "{%0,%1,%2,%3}, {%4,%5,%6,%7}, {%8,%9}, {%0,%1,%2,%3};"
                 : "+f"(c[0]), "+f"(c[1]), "+f"(c[2]), "+f"(c[3])
                 : "r"(a[0]), "r"(a[1]), "r"(a[2]), "r"(a[3]), "r"(b[0]), "r"(b[1]));
}
__device__ __forceinline__ float4 bf4_to_f4(uint2 v) {
    __nv_bfloat162 lo = *(__nv_bfloat162*)&v.x;
    __nv_bfloat162 hi = *(__nv_bfloat162*)&v.y;
    float2 a = __bfloat1622float2(lo);
    float2 b = __bfloat1622float2(hi);
    return make_float4(a.x, a.y, b.x, b.y);
}

// ---------------------------------------------------------------------------
// Merged conversions: activations (z: 0=x, 1=x_ref) and weights (z: 0..3)
// ---------------------------------------------------------------------------
__global__ void __launch_bounds__(256)
convx_kernel(const float* __restrict__ x, const float* __restrict__ xref,
             __nv_bfloat16* __restrict__ xb, __nv_bfloat16* __restrict__ xrefb)
{
    const float* in = blockIdx.z ? xref : x;
    __nv_bfloat16* out = blockIdx.z ? xrefb : xb;
    int i = (blockIdx.x * 256 + threadIdx.x) * 8;
    float4 v0 = *(const float4*)(in + i);
    float4 v1 = *(const float4*)(in + i + 4);
    __nv_bfloat162 o[4];
    o[0] = __floats2bfloat162_rn(v0.x, v0.y);
    o[1] = __floats2bfloat162_rn(v0.z, v0.w);
    o[2] = __floats2bfloat162_rn(v1.x, v1.y);
    o[3] = __floats2bfloat162_rn(v1.z, v1.w);
    *(uint4*)(out + i) = *(const uint4*)o;
}

__global__ void __launch_bounds__(256)
convw_kernel(const float* __restrict__ w0, const float* __restrict__ w1,
             const float* __restrict__ w2, const float* __restrict__ w3,
             __nv_bfloat16* __restrict__ out)
{
    const int z = blockIdx.z;
    const float* in = (z == 0) ? w0 : (z == 1) ? w1 : (z == 2) ? w2 : w3;
    __nv_bfloat16* o = out + (size_t)z * (CINT * CIN);
    int i = (blockIdx.x * 256 + threadIdx.x) * 8;
    float4 v0 = *(const float4*)(in + i);
    float4 v1 = *(const float4*)(in + i + 4);
    __nv_bfloat162 p[4];
    p[0] = __floats2bfloat162_rn(v0.x, v0.y);
    p[1] = __floats2bfloat162_rn(v0.z, v0.w);
    p[2] = __floats2bfloat162_rn(v1.x, v1.y);
    p[3] = __floats2bfloat162_rn(v1.z, v1.w);
    *(uint4*)(o + i) = *(const uint4*)p;
}

// ---------------------------------------------------------------------------
// bf16 tensor-core GEMM (mma.sync), BK=32, 3-stage cp.async pipeline, ONE
// barrier per k-tile (round-11 proven config). Output either bf16 (Obf != 0)
// or fp32 with optional residual.
// ---------------------------------------------------------------------------
#define AS_STRIDE 40
#define BS_STRIDE 136
#define AS_ELEMS (128 * AS_STRIDE)
#define BS_ELEMS (32 * BS_STRIDE)
#define AS_BYTES (AS_ELEMS * 2)
#define BS_BYTES (BS_ELEMS * 2)
#define GEMM_STAGES 3
#define GEMM_SMEM (GEMM_STAGES * (AS_BYTES + BS_BYTES))   // 56832

__global__ void __launch_bounds__(256)
bgemm_kernel(const __nv_bfloat16* __restrict__ W, const __nv_bfloat16* __restrict__ Z,
             const float* __restrict__ bias, const float* __restrict__ res,
             float* __restrict__ O, __nv_bfloat16* __restrict__ Obf,
             int M, int K, int P)
{
    extern __shared__ __align__(16) char dsm[];

    const int b  = blockIdx.z;
    const __nv_bfloat16* Zb = Z + (size_t)b * K * P;

    const int m0 = blockIdx.y * 128;
    const int n0 = blockIdx.x * 128;
    const int tid  = threadIdx.x;
    const int lane = tid & 31;
    const int wid  = tid >> 5;
    const int wm = wid & 1;
    const int wn = wid >> 1;

    const uint32_t smem0 = sptr(dsm);
    const uint32_t bbase0 = smem0 + GEMM_STAGES * AS_BYTES;

    const int a_r = tid >> 2;
    const int a_c = tid & 3;
    const int b_r = tid >> 4;
    const int b_c = tid & 15;

    float acc[4][4][4];
#pragma unroll
    for (int mt = 0; mt < 4; mt++)
#pragma unroll
        for (int nt = 0; nt < 4; nt++)
#pragma unroll
            for (int i = 0; i < 4; i++) acc[mt][nt][i] = 0.f;

    const int nk = K >> 5;

#pragma unroll
    for (int pt = 0; pt < 2; pt++) {
        const uint32_t as = smem0 + pt * AS_BYTES;
        const uint32_t bs = bbase0 + pt * BS_BYTES;
        const int k0 = pt * 32;
        cp16(as + (uint32_t)((a_r)      * AS_STRIDE + a_c * 8) * 2, W  + (size_t)(m0 + a_r)      * K + k0 + a_c * 8);
        cp16(as + (uint32_t)((a_r + 64) * AS_STRIDE + a_c * 8) * 2, W  + (size_t)(m0 + a_r + 64) * K + k0 + a_c * 8);
        cp16(bs + (uint32_t)((b_r)      * BS_STRIDE + b_c * 8) * 2, Zb + (size_t)(k0 + b_r)      * P + n0 + b_c * 8);
        cp16(bs + (uint32_t)((b_r + 16) * BS_STRIDE + b_c * 8) * 2, Zb + (size_t)(k0 + b_r + 16) * P + n0 + b_c * 8);
        cp_commit();
    }

    int s = 0;
    for (int kt = 0; kt < nk; kt++) {
        if (kt + 1 < nk) cp_wait1(); else cp_wait0();
        __syncthreads();

        if (kt + 2 < nk) {
            int sp = s + 2; if (sp >= GEMM_STAGES) sp -= GEMM_STAGES;
            const uint32_t as = smem0 + sp * AS_BYTES;
            const uint32_t bs = bbase0 + sp * BS_BYTES;
            const int k0 = (kt + 2) * 32;
            cp16(as + (uint32_t)((a_r)      * AS_STRIDE + a_c * 8) * 2, W  + (size_t)(m0 + a_r)      * K + k0 + a_c * 8);
            cp16(as + (uint32_t)((a_r + 64) * AS_STRIDE + a_c * 8) * 2, W  + (size_t)(m0 + a_r + 64) * K + k0 + a_c * 8);
            cp16(bs + (uint32_t)((b_r)      * BS_STRIDE + b_c * 8) * 2, Zb + (size_t)(k0 + b_r)      * P + n0 + b_c * 8);
            cp16(bs + (uint32_t)((b_r + 16) * BS_STRIDE + b_c * 8) * 2, Zb + (size_t)(k0 + b_r + 16) * P + n0 + b_c * 8);
            cp_commit();
        }

        const uint32_t as = smem0 + s * AS_BYTES;
        const uint32_t bs = bbase0 + s * BS_BYTES;

#pragma unroll
        for (int kk = 0; kk < 2; kk++) {
            const int k0 = kk * 16;
            uint32_t a[4][4];
            const uint32_t a_base = as + (uint32_t)(((wm * 64 + (lane & 15)) * AS_STRIDE) + k0 + (lane >> 4) * 8) * 2;
#pragma unroll
            for (int mt = 0; mt < 4; mt++)
                ldsmx4(a[mt], a_base + (uint32_t)(mt * 16 * AS_STRIDE) * 2);

            uint32_t bb[4][2];
            const uint32_t b_base = bs + (uint32_t)((k0 + (lane & 15)) * BS_STRIDE + wn * 32 + (lane >> 4) * 8) * 2;
            {
                uint32_t r[4];
                ldsmx4t(r, b_base);
                bb[0][0] = r[0]; bb[0][1] = r[1];
                bb[1][0] = r[2]; bb[1][1] = r[3];
                ldsmx4t(r, b_base + 16 * 2);
                bb[2][0] = r[0]; bb[2][1] = r[1];
                bb[3][0] = r[2]; bb[3][1] = r[3];
            }

#pragma unroll
            for (int mt = 0; mt < 4; mt++)
#pragma unroll
                for (int nt = 0; nt < 4; nt++)
                    mma16816(acc[mt][nt], a[mt], bb[nt]);
        }
        if (++s == GEMM_STAGES) s = 0;
    }

    if (Obf) {
        __nv_bfloat16* Ob = Obf + (size_t)b * M * P;
#pragma unroll
        for (int mt = 0; mt < 4; mt++) {
            const int r0 = m0 + wm * 64 + mt * 16 + (lane >> 2);
            const int r1 = r0 + 8;
            const float bv0 = bias[r0];
            const float bv1 = bias[r1];
#pragma unroll
            for (int nt = 0; nt < 4; nt++) {
                const int col = n0 + wn * 32 + nt * 8 + (lane & 3) * 2;
                __nv_bfloat162 o0 = __floats2bfloat162_rn(acc[mt][nt][0] + bv0,
                                                          acc[mt][nt][1] + bv0);
                __nv_bfloat162 o1 = __floats2bfloat162_rn(acc[mt][nt][2] + bv1,
                                                          acc[mt][nt][3] + bv1);
                *(uint32_t*)&Ob[(size_t)r0 * P + col] = *(uint32_t*)&o0;
                *(uint32_t*)&Ob[(size_t)r1 * P + col] = *(uint32_t*)&o1;
            }
        }
    } else {
        float* Ob = O + (size_t)b * M * P;
        const float* Rb = res ? res + (size_t)b * M * P : nullptr;
#pragma unroll
        for (int mt = 0; mt < 4; mt++) {
            const int r0 = m0 + wm * 64 + mt * 16 + (lane >> 2);
            const int r1 = r0 + 8;
            const float bv0 = bias[r0];
            const float bv1 = bias[r1];
#pragma unroll
            for (int nt = 0; nt < 4; nt++) {
                const int col = n0 + wn * 32 + nt * 8 + (lane & 3) * 2;
                float2 v0 = make_float2(acc[mt][nt][0] + bv0, acc[mt][nt][1] + bv0);
                float2 v1 = make_float2(acc[mt][nt][2] + bv1, acc[mt][nt][3] + bv1);
                if (Rb) {
                    float2 t0 = *(const float2*)&Rb[(size_t)r0 * P + col];
                    float2 t1 = *(const float2*)&Rb[(size_t)r1 * P + col];
                    v0.x += t0.x; v0.y += t0.y;
                    v1.x += t1.x; v1.y += t1.y;
                }
                *(float2*)&Ob[(size_t)r0 * P + col] = v0;
                *(float2*)&Ob[(size_t)r1 * P + col] = v1;
            }
        }
    }
}

// ---------------------------------------------------------------------------
// Correlation, 2-pixel y-blocking + register-prefetch pipeline (CCH=4).
// theta/phi read as bf16 (uint2 = 4 elems), converted to fp32 at the STS;
// smem + compute loops identical to the proven round-11 version.
// ---------------------------------------------------------------------------
#define CTW 32
#define CTH2 16
#define CWW (CTW + 2 * DD)    // 40
#define CWH (CTH2 + 2 * DD)   // 24
#define CCH 4
#define CPB (CINT / CSPLIT)   // 256
#define TH_F4 ((CCH * CTH2 * CTW) / 4)   // 512 quads
#define PH_F4 ((CCH * CWH * CWW) / 4)    // 960 quads

__global__ void __launch_bounds__(256, 1)
corr_kernel(const __nv_bfloat16* __restrict__ theta,
            const __nv_bfloat16* __restrict__ phi,
            float* __restrict__ pwpart)
{
    __shared__ __align__(16) float th_s[CCH * CTH2 * CTW];   // 8 KB
    __shared__ __align__(16) float ph_s[CCH * CWH * CWW];    // 15 KB

    const int z  = blockIdx.z;
    const int b  = z >> 1;
    const int ci = z & 1;
    const int ch0 = ci * CPB;
    const int w0 = blockIdx.x * CTW;
    const int h0 = blockIdx.y * CTH2;
    const int tid = threadIdx.x;
    const int tx = tid & 31;
    const int ty = tid >> 5;          // 0..7 -> pixel rows 2ty, 2ty+1

    const __nv_bfloat16* thb = theta + (size_t)b * CINT * PP;
    const __nv_bfloat16* phb = phi   + (size_t)b * CINT * PP;

    float accA[QQ], accB[QQ];
#pragma unroll
    for (int q = 0; q < QQ; q++) { accA[q] = 0.f; accB[q] = 0.f; }

    uint2 thr[2];
    uint2 phr[4];

#define CORR_LOAD(c0)                                                          \
    {                                                                          \
        _Pragma("unroll")                                                      \
        for (int j = 0; j < 2; j++) {                                          \
            const int idx4 = tid * 2 + j;                                      \
            const int cc  = idx4 >> 7;                                         \
            const int rem = idx4 & 127;                                        \
            const int r   = rem >> 3;                                          \
            const int cg  = rem & 7;                                           \
            thr[j] = *(const uint2*)&thb[(size_t)((c0) + cc) * PP +            \
                                         (h0 + r) * WW + w0 + cg * 4];         \
        }                                                                      \
        _Pragma("unroll")                                                      \
        for (int j = 0; j < 4; j++) {                                          \
            const int t = tid + j * 256;                                       \
            if (t < PH_F4) {                                                   \
                const int cc  = t / 240;                                       \
                const int rem = t - cc * 240;                                  \
                const int r   = rem / 10;                                      \
                const int cg  = rem - r * 10;                                  \
                const int hh   = h0 - DD + r;                                  \
                const int gcol = w0 - DD + cg * 4;                             \
                uint2 v = make_uint2(0u, 0u);                                  \
                if (hh >= 0 && hh < HH && gcol >= 0 && gcol < WW)              \
                    v = *(const uint2*)&phb[(size_t)((c0) + cc) * PP +         \
                                            hh * WW + gcol];                   \
                phr[j] = v;                                                    \
            }                                                                  \
        }                                                                      \
    }

    CORR_LOAD(ch0);

    const int nch = CPB / CCH;   // 64 chunks
    for (int c = 0; c < nch; c++) {
#pragma unroll
        for (int j = 0; j < 2; j++)
            ((float4*)th_s)[tid * 2 + j] = bf4_to_f4(thr[j]);
#pragma unroll
        for (int j = 0; j < 4; j++) {
            const int t = tid + j * 256;
            if (t < PH_F4) ((float4*)ph_s)[t] = bf4_to_f4(phr[j]);
        }
        __syncthreads();

        if (c + 1 < nch) CORR_LOAD(ch0 + (c + 1) * CCH);

#pragma unroll
        for (int cc = 0; cc < CCH; cc++) {
            const float t0 = th_s[cc * (CTH2 * CTW) + (2 * ty)     * CTW + tx];
            const float t1 = th_s[cc * (CTH2 * CTW) + (2 * ty + 1) * CTW + tx];
            const float* pr = &ph_s[cc * (CWH * CWW)];
#pragma unroll
            for (int rr = 0; rr < 10; rr++) {
                const float* row = &pr[(2 * ty + rr) * CWW + tx];
#pragma unroll
                for (int dx = 0; dx < 9; dx++) {
                    const float v = row[dx];
                    if (rr < 9) accA[rr * 9 + dx] += t0 * v;
                    if (rr >= 1) accB[(rr - 1) * 9 + dx] += t1 * v;
                }
            }
        }
        __syncthreads();
    }
#undef CORR_LOAD

    const int pixA = (h0 + 2 * ty) * WW + (w0 + tx);
    float* bp = pwpart + ((size_t)(ci * NB + b) * QQ) * PP;
#pragma unroll
    for (int q = 0; q < QQ; q++) {
        bp[(size_t)q * PP + pixA]      = accA[q];
        bp[(size_t)q * PP + pixA + WW] = accB[q];
    }
}

// ---------------------------------------------------------------------------
// Softmax over Q (sums the 2 channel-split partials, applies scale)
// ---------------------------------------------------------------------------
__global__ void __launch_bounds__(128)
softmax_kernel(const float* __restrict__ part, float* __restrict__ pw)
{
    const int t = blockIdx.x * 128 + threadIdx.x;
    const int b = t / PP;
    const int pix = t - b * PP;
    const size_t qp = (size_t)QQ * PP;
    const float scale = 256.0f / sqrtf((float)WW) / (float)CINT;

    float v[QQ];
    float m = -1e30f;
#pragma unroll
    for (int q = 0; q < QQ; q++) {
        const size_t off = (size_t)q * PP + pix;
        float s = part[(size_t)(0 * NB + b) * qp + off]
                + part[(size_t)(1 * NB + b) * qp + off];
        v[q] = s * scale;
        m = fmaxf(m, v[q]);
    }
    float s = 0.f;
#pragma unroll
    for (int q = 0; q < QQ; q++) { v[q] = __expf(v[q] - m); s += v[q]; }
    const float inv = 1.0f / s;
    float* pwb = pw + (size_t)b * qp + pix;
#pragma unroll
    for (int q = 0; q < QQ; q++) pwb[(size_t)q * PP] = v[q] * inv;
}

// ---------------------------------------------------------------------------
// Assemble, 2-pixel y-blocking + register-prefetch pipeline (CCH=4).
// g read as bf16, converted at STS; compute loop identical.
// ---------------------------------------------------------------------------
__global__ void __launch_bounds__(256, 1)
assemble_kernel(const float* __restrict__ pw,
                const __nv_bfloat16* __restrict__ g,
                __nv_bfloat16* __restrict__ y)
{
    __shared__ __align__(16) float gs[CCH * CWH * CWW];   // 15 KB

    const int z  = blockIdx.z;
    const int b  = z >> 3;
    const int c0base = (z & 7) * (CINT / ASPLIT); // 64 channels
    const int w0 = blockIdx.x * CTW;
    const int h0 = blockIdx.y * CTH2;
    const int tid = threadIdx.x;
    const int tx = tid & 31;
    const int ty = tid >> 5;

    const __nv_bfloat16* gb = g + (size_t)b * CINT * PP;
    const float* pwb = pw + (size_t)b * QQ * PP;
    __nv_bfloat16* yb = y + (size_t)b * CINT * PP;

    const int pixA = (h0 + 2 * ty) * WW + (w0 + tx);
    const int pixB = pixA + WW;

    float rpwA[QQ], rpwB[QQ];
#pragma unroll
    for (int q = 0; q < QQ; q++) {
        rpwA[q] = pwb[(size_t)q * PP + pixA];
        rpwB[q] = pwb[(size_t)q * PP + pixB];
    }

    uint2 gr4[4];

#define ASM_LOAD(c0)                                                           \
    {                                                                          \
        _Pragma("unroll")                                                      \
        for (int j = 0; j < 4; j++) {                                          \
            const int t = tid + j * 256;                                       \
            if (t < PH_F4) {                                                   \
                const int cc  = t / 240;                                       \
                const int rem = t - cc * 240;                                  \
                const int r   = rem / 10;                                      \
                const int cg  = rem - r * 10;                                  \
                const int hh   = h0 - DD + r;                                  \
                const int gcol = w0 - DD + cg * 4;                             \
                uint2 v = make_uint2(0u, 0u);                                  \
                if (hh >= 0 && hh < HH && gcol >= 0 && gcol < WW)              \
                    v = *(const uint2*)&gb[(size_t)((c0) + cc) * PP +          \
                                           hh * WW + gcol];                    \
                gr4[j] = v;                                                    \
            }                                                                  \
        }                                                                      \
    }

    ASM_LOAD(c0base);

    const int nch = (CINT / ASPLIT) / CCH;   // 16 chunks
    for (int c = 0; c < nch; c++) {
#pragma unroll
        for (int j = 0; j < 4; j++) {
            const int t = tid + j * 256;
            if (t < PH_F4) ((float4*)gs)[t] = bf4_to_f4(gr4[j]);
        }
        __syncthreads();

        if (c + 1 < nch) ASM_LOAD(c0base + (c + 1) * CCH);

        const int c0 = c0base + c * CCH;
#pragma unroll
        for (int cc = 0; cc < CCH; cc++) {
            const float* grp = &gs[cc * (CWH * CWW)];
            float aA = 0.f, aB = 0.f;
#pragma unroll
            for (int rr = 0; rr < 10; rr++) {
                const float* row = &grp[(2 * ty + rr) * CWW + tx];
#pragma unroll
                for (int dx = 0; dx < 9; dx++) {
                    const float v = row[dx];
                    if (rr < 9) aA += rpwA[rr * 9 + dx] * v;
                    if (rr >= 1) aB += rpwB[(rr - 1) * 9 + dx] * v;
                }
            }
            yb[(size_t)(c0 + cc) * PP + pixA] = __float2bfloat16(aA);
            yb[(size_t)(c0 + cc) * PP + pixB] = __float2bfloat16(aB);
        }
        __syncthreads();
    }
#undef ASM_LOAD
}

// ---------------------------------------------------------------------------
// Launch
// ---------------------------------------------------------------------------
extern "C" void kernel_launch(void* const* d_in, const int* in_sizes, int n_in,
                              void* d_out, int out_size)
{
    (void)in_sizes; (void)n_in; (void)out_size;

    const float* x       = (const float*)d_in[0];
    const float* x_ref   = (const float*)d_in[1];
    const float* w_g     = (const float*)d_in[2];
    const float* b_g     = (const float*)d_in[3];
    const float* w_theta = (const float*)d_in[4];
    const float* b_theta = (const float*)d_in[5];
    const float* w_phi   = (const float*)d_in[6];
    const float* b_phi   = (const float*)d_in[7];
    const float* w_out   = (const float*)d_in[8];
    const float* b_out   = (const float*)d_in[9];
    float* out = (float*)d_out;

    __nv_bfloat16 *xb, *xrefb, *wb, *yb, *theta, *gbuf, *phi;
    float *pwpart, *pw;
    cudaGetSymbolAddress((void**)&xb,     g_xb);
    cudaGetSymbolAddress((void**)&xrefb,  g_xrefb);
    cudaGetSymbolAddress((void**)&wb,     g_wb);
    cudaGetSymbolAddress((void**)&theta,  g_theta);
    cudaGetSymbolAddress((void**)&gbuf,   g_g);
    cudaGetSymbolAddress((void**)&phi,    g_phi);
    cudaGetSymbolAddress((void**)&pwpart, g_pwpart);
    cudaGetSymbolAddress((void**)&pw,     g_pw);
    cudaGetSymbolAddress((void**)&yb,     g_yb);

    cudaFuncSetAttribute(bgemm_kernel, cudaFuncAttributeMaxDynamicSharedMemorySize, GEMM_SMEM);

    const int WSZ = CINT * CIN;
    __nv_bfloat16* wtb = wb + 0 * WSZ;
    __nv_bfloat16* wgb = wb + 1 * WSZ;
    __nv_bfloat16* wpb = wb + 2 * WSZ;
    __nv_bfloat16* wob = wb + 3 * WSZ;

    // conversions (2 launches)
    const int nx = NB * CIN * PP;
    dim3 cxg(nx / (256 * 8), 1, 2);
    convx_kernel<<<cxg, 256>>>(x, x_ref, xb, xrefb);
    dim3 cwg(WSZ / (256 * 8), 1, 4);
    convw_kernel<<<cwg, 256>>>(w_theta, w_g, w_phi, w_out, wb);

    // 1x1 convs (tensor-core GEMMs, 3-stage pipeline, bf16 outputs)
    dim3 blk(256);
    dim3 gg1(PP / 128, CINT / 128, NB);     // (72, 4, 4)
    bgemm_kernel<<<gg1, blk, GEMM_SMEM>>>(wtb, xb,    b_theta, nullptr, nullptr, theta, CINT, CIN, PP);
    bgemm_kernel<<<gg1, blk, GEMM_SMEM>>>(wgb, xrefb, b_g,     nullptr, nullptr, gbuf,  CINT, CIN, PP);
    bgemm_kernel<<<gg1, blk, GEMM_SMEM>>>(wpb, xrefb, b_phi,   nullptr, nullptr, phi,   CINT, CIN, PP);

    // correlation partials + softmax
    dim3 cg(WW / CTW, HH / CTH2, NB * CSPLIT);   // (3, 6, 8) = 144 blocks
    corr_kernel<<<cg, blk>>>(theta, phi, pwpart);
    softmax_kernel<<<(NB * PP) / 128, 128>>>(pwpart, pw);

    // assemble (bf16 output)
    dim3 ag(WW / CTW, HH / CTH2, NB * ASPLIT);   // (3, 6, 32) = 576 blocks
    assemble_kernel<<<ag, blk>>>(pw, gbuf, yb);

    // final conv + residual (fp32 output)
    dim3 gg2(PP / 128, CIN / 128, NB);           // (72, 8, 4)
    bgemm_kernel<<<gg2, blk, GEMM_SMEM>>>(wob, yb, b_out, x, out, nullptr, CIN, CINT, PP);
}

// round 16
// speedup vs baseline: 1.4877x; 1.0731x over previous
#include <cuda_runtime.h>
#include <cuda_bf16.h>
#include <math.h>
#include <stdint.h>

// Problem constants
#define NB    4
#define CIN   1024
#define CINT  512
#define HH    96
#define WW    96
#define PP    (HH * WW)      // 9216
#define DD    4
#define QQ    81
#define CSPLIT 2             // corr channel split
#define ASPLIT 4             // assemble channel split

// ---------------------------------------------------------------------------
// Scratch (device globals; no allocation allowed)
// ---------------------------------------------------------------------------
__device__ __align__(128) __nv_bfloat16 g_xb   [NB * CIN  * PP];
__device__ __align__(128) __nv_bfloat16 g_xrefb[NB * CIN  * PP];
__device__ __align__(128) __nv_bfloat16 g_wb   [4 * CINT * CIN];   // theta,g,phi,out
__device__ __align__(128) float g_theta [NB * CINT * PP];
__device__ __align__(128) float g_g     [NB * CINT * PP];
__device__ __align__(128) float g_phi   [NB * CINT * PP];
__device__ __align__(128) float g_pwpart[CSPLIT * NB * QQ * PP];
__device__ __align__(128) float g_pw    [NB * QQ * PP];
__device__ __align__(128) __nv_bfloat16 g_yb   [NB * CINT * PP];

// ---------------------------------------------------------------------------
// Helpers (legacy path: cp.async + ldmatrix + mma.sync; no tcgen05 — the
// toolchain targets sm_103 without the 'a' feature set)
// ---------------------------------------------------------------------------
__device__ __forceinline__ uint32_t sptr(const void* p) {
    return (uint32_t)__cvta_generic_to_shared(p);
}
__device__ __forceinline__ void cp16(uint32_t dst, const void* src) {
    asm volatile("cp.async.cg.shared.global [%0], [%1], 16;" :: "r"(dst), "l"(src));
}
__device__ __forceinline__ void cp_commit() {
    asm volatile("cp.async.commit_group;");
}
__device__ __forceinline__ void cp_wait0() {
    asm volatile("cp.async.wait_group 0;");
}
__device__ __forceinline__ void cp_wait1() {
    asm volatile("cp.async.wait_group 1;");
}
__device__ __forceinline__ void ldsmx4(uint32_t* r, uint32_t addr) {
    asm volatile("ldmatrix.sync.aligned.m8n8.x4.shared.b16 {%0,%1,%2,%3}, [%4];"
                 : "=r"(r[0]), "=r"(r[1]), "=r"(r[2]), "=r"(r[3]) : "r"(addr));
}
__device__ __forceinline__ void ldsmx4t(uint32_t* r, uint32_t addr) {
    asm volatile("ldmatrix.sync.aligned.m8n8.x4.trans.shared.b16 {%0,%1,%2,%3}, [%4];"
                 : "=r"(r[0]), "=r"(r[1]), "=r"(r[2]), "=r"(r[3]) : "r"(addr));
}
__device__ __forceinline__ void mma16816(float* c, const uint32_t* a, const uint32_t* b) {
    asm volatile("mma.sync.aligned.m16n8k16.row.col.f32.bf16.bf16.f32 "
                 "{%0,%1,%2,%3}, {%4,%5,%6,%7}, {%8,%9}, {%0,%1,%2,%3};"
                 : "+f"(c[0]), "+f"(c[1]), "+f"(c[2]), "+f"(c[3])
                 : "r"(a[0]), "r"(a[1]), "r"(a[2]), "r"(a[3]), "r"(b[0]), "r"(b[1]));
}

// ---------------------------------------------------------------------------
// Merged conversions: activations (z: 0=x, 1=x_ref) and weights (z: 0..3)
// ---------------------------------------------------------------------------
__global__ void __launch_bounds__(256)
convx_kernel(const float* __restrict__ x, const float* __restrict__ xref,
             __nv_bfloat16* __restrict__ xb, __nv_bfloat16* __restrict__ xrefb)
{
    const float* in = blockIdx.z ? xref : x;
    __nv_bfloat16* out = blockIdx.z ? xrefb : xb;
    int i = (blockIdx.x * 256 + threadIdx.x) * 8;
    float4 v0 = *(const float4*)(in + i);
    float4 v1 = *(const float4*)(in + i + 4);
    __nv_bfloat162 o[4];
    o[0] = __floats2bfloat162_rn(v0.x, v0.y);
    o[1] = __floats2bfloat162_rn(v0.z, v0.w);
    o[2] = __floats2bfloat162_rn(v1.x, v1.y);
    o[3] = __floats2bfloat162_rn(v1.z, v1.w);
    *(uint4*)(out + i) = *(const uint4*)o;
}

__global__ void __launch_bounds__(256)
convw_kernel(const float* __restrict__ w0, const float* __restrict__ w1,
             const float* __restrict__ w2, const float* __restrict__ w3,
             __nv_bfloat16* __restrict__ out)
{
    const int z = blockIdx.z;
    const float* in = (z == 0) ? w0 : (z == 1) ? w1 : (z == 2) ? w2 : w3;
    __nv_bfloat16* o = out + (size_t)z * (CINT * CIN);
    int i = (blockIdx.x * 256 + threadIdx.x) * 8;
    float4 v0 = *(const float4*)(in + i);
    float4 v1 = *(const float4*)(in + i + 4);
    __nv_bfloat162 p[4];
    p[0] = __floats2bfloat162_rn(v0.x, v0.y);
    p[1] = __floats2bfloat162_rn(v0.z, v0.w);
    p[2] = __floats2bfloat162_rn(v1.x, v1.y);
    p[3] = __floats2bfloat162_rn(v1.z, v1.w);
    *(uint4*)(o + i) = *(const uint4*)p;
}

// ---------------------------------------------------------------------------
// bf16 tensor-core GEMM (mma.sync), BK=32, 3-stage cp.async pipeline, ONE
// barrier per k-tile (round-11 proven config). HAS_RES selects the epilogue
// at compile time.
// ---------------------------------------------------------------------------
#define AS_STRIDE 40
#define BS_STRIDE 136
#define AS_ELEMS (128 * AS_STRIDE)
#define BS_ELEMS (32 * BS_STRIDE)
#define AS_BYTES (AS_ELEMS * 2)
#define BS_BYTES (BS_ELEMS * 2)
#define GEMM_STAGES 3
#define GEMM_SMEM (GEMM_STAGES * (AS_BYTES + BS_BYTES))   // 56832

template <bool HAS_RES>
__global__ void __launch_bounds__(256)
bgemm_kernel(const __nv_bfloat16* __restrict__ W, const __nv_bfloat16* __restrict__ Z,
             const float* __restrict__ bias, const float* __restrict__ res,
             float* __restrict__ O, int M, int K, int P)
{
    extern __shared__ __align__(16) char dsm[];

    const int b  = blockIdx.z;
    const __nv_bfloat16* Zb = Z + (size_t)b * K * P;
    float*       Ob = O + (size_t)b * M * P;
    const float* Rb = HAS_RES ? res + (size_t)b * M * P : nullptr;

    const int m0 = blockIdx.y * 128;
    const int n0 = blockIdx.x * 128;
    const int tid  = threadIdx.x;
    const int lane = tid & 31;
    const int wid  = tid >> 5;
    const int wm = wid & 1;
    const int wn = wid >> 1;

    const uint32_t smem0 = sptr(dsm);
    const uint32_t bbase0 = smem0 + GEMM_STAGES * AS_BYTES;

    const int a_r = tid >> 2;
    const int a_c = tid & 3;
    const int b_r = tid >> 4;
    const int b_c = tid & 15;

    float acc[4][4][4];
#pragma unroll
    for (int mt = 0; mt < 4; mt++)
#pragma unroll
        for (int nt = 0; nt < 4; nt++)
#pragma unroll
            for (int i = 0; i < 4; i++) acc[mt][nt][i] = 0.f;

    const int nk = K >> 5;

#pragma unroll
    for (int pt = 0; pt < 2; pt++) {
        const uint32_t as = smem0 + pt * AS_BYTES;
        const uint32_t bs = bbase0 + pt * BS_BYTES;
        const int k0 = pt * 32;
        cp16(as + (uint32_t)((a_r)      * AS_STRIDE + a_c * 8) * 2, W  + (size_t)(m0 + a_r)      * K + k0 + a_c * 8);
        cp16(as + (uint32_t)((a_r + 64) * AS_STRIDE + a_c * 8) * 2, W  + (size_t)(m0 + a_r + 64) * K + k0 + a_c * 8);
        cp16(bs + (uint32_t)((b_r)      * BS_STRIDE + b_c * 8) * 2, Zb + (size_t)(k0 + b_r)      * P + n0 + b_c * 8);
        cp16(bs + (uint32_t)((b_r + 16) * BS_STRIDE + b_c * 8) * 2, Zb + (size_t)(k0 + b_r + 16) * P + n0 + b_c * 8);
        cp_commit();
    }

    int s = 0;
    for (int kt = 0; kt < nk; kt++) {
        if (kt + 1 < nk) cp_wait1(); else cp_wait0();
        __syncthreads();

        if (kt + 2 < nk) {
            int sp = s + 2; if (sp >= GEMM_STAGES) sp -= GEMM_STAGES;
            const uint32_t as = smem0 + sp * AS_BYTES;
            const uint32_t bs = bbase0 + sp * BS_BYTES;
            const int k0 = (kt + 2) * 32;
            cp16(as + (uint32_t)((a_r)      * AS_STRIDE + a_c * 8) * 2, W  + (size_t)(m0 + a_r)      * K + k0 + a_c * 8);
            cp16(as + (uint32_t)((a_r + 64) * AS_STRIDE + a_c * 8) * 2, W  + (size_t)(m0 + a_r + 64) * K + k0 + a_c * 8);
            cp16(bs + (uint32_t)((b_r)      * BS_STRIDE + b_c * 8) * 2, Zb + (size_t)(k0 + b_r)      * P + n0 + b_c * 8);
            cp16(bs + (uint32_t)((b_r + 16) * BS_STRIDE + b_c * 8) * 2, Zb + (size_t)(k0 + b_r + 16) * P + n0 + b_c * 8);
            cp_commit();
        }

        const uint32_t as = smem0 + s * AS_BYTES;
        const uint32_t bs = bbase0 + s * BS_BYTES;

#pragma unroll
        for (int kk = 0; kk < 2; kk++) {
            const int k0 = kk * 16;
            uint32_t a[4][4];
            const uint32_t a_base = as + (uint32_t)(((wm * 64 + (lane & 15)) * AS_STRIDE) + k0 + (lane >> 4) * 8) * 2;
#pragma unroll
            for (int mt = 0; mt < 4; mt++)
                ldsmx4(a[mt], a_base + (uint32_t)(mt * 16 * AS_STRIDE) * 2);

            uint32_t bb[4][2];
            const uint32_t b_base = bs + (uint32_t)((k0 + (lane & 15)) * BS_STRIDE + wn * 32 + (lane >> 4) * 8) * 2;
            {
                uint32_t r[4];
                ldsmx4t(r, b_base);
                bb[0][0] = r[0]; bb[0][1] = r[1];
                bb[1][0] = r[2]; bb[1][1] = r[3];
                ldsmx4t(r, b_base + 16 * 2);
                bb[2][0] = r[0]; bb[2][1] = r[1];
                bb[3][0] = r[2]; bb[3][1] = r[3];
            }

#pragma unroll
            for (int mt = 0; mt < 4; mt++)
#pragma unroll
                for (int nt = 0; nt < 4; nt++)
                    mma16816(acc[mt][nt], a[mt], bb[nt]);
        }
        if (++s == GEMM_STAGES) s = 0;
    }

#pragma unroll
    for (int mt = 0; mt < 4; mt++) {
        const int r0 = m0 + wm * 64 + mt * 16 + (lane >> 2);
        const int r1 = r0 + 8;
        const float bv0 = bias[r0];
        const float bv1 = bias[r1];
#pragma unroll
        for (int nt = 0; nt < 4; nt++) {
            const int col = n0 + wn * 32 + nt * 8 + (lane & 3) * 2;
            float2 v0 = make_float2(acc[mt][nt][0] + bv0, acc[mt][nt][1] + bv0);
            float2 v1 = make_float2(acc[mt][nt][2] + bv1, acc[mt][nt][3] + bv1);
            if (HAS_RES) {
                float2 t0 = *(const float2*)&Rb[(size_t)r0 * P + col];
                float2 t1 = *(const float2*)&Rb[(size_t)r1 * P + col];
                v0.x += t0.x; v0.y += t0.y;
                v1.x += t1.x; v1.y += t1.y;
            }
            *(float2*)&Ob[(size_t)r0 * P + col] = v0;
            *(float2*)&Ob[(size_t)r1 * P + col] = v1;
        }
    }
}

// ---------------------------------------------------------------------------
// Correlation, 2-pixel y-blocking + register-prefetch pipeline (CCH=4).
// (round-11 proven version, unchanged)
// ---------------------------------------------------------------------------
#define CTW 32
#define CTH2 16
#define CWW (CTW + 2 * DD)    // 40
#define CWH (CTH2 + 2 * DD)   // 24
#define CCH 4
#define CPB (CINT / CSPLIT)   // 256
#define TH_F4 ((CCH * CTH2 * CTW) / 4)   // 512 float4
#define PH_F4 ((CCH * CWH * CWW) / 4)    // 960 float4

__global__ void __launch_bounds__(256, 1)
corr_kernel(const float* __restrict__ theta,
            const float* __restrict__ phi,
            float* __restrict__ pwpart)
{
    __shared__ __align__(16) float th_s[CCH * CTH2 * CTW];   // 8 KB
    __shared__ __align__(16) float ph_s[CCH * CWH * CWW];    // 15 KB

    const int z  = blockIdx.z;
    const int b  = z >> 1;
    const int ci = z & 1;
    const int ch0 = ci * CPB;
    const int w0 = blockIdx.x * CTW;
    const int h0 = blockIdx.y * CTH2;
    const int tid = threadIdx.x;
    const int tx = tid & 31;
    const int ty = tid >> 5;          // 0..7 -> pixel rows 2ty, 2ty+1

    const float* thb = theta + (size_t)b * CINT * PP;
    const float* phb = phi   + (size_t)b * CINT * PP;

    float accA[QQ], accB[QQ];
#pragma unroll
    for (int q = 0; q < QQ; q++) { accA[q] = 0.f; accB[q] = 0.f; }

    float4 thr[2];
    float4 phr[4];

#define CORR_LOAD(c0)                                                          \
    {                                                                          \
        _Pragma("unroll")                                                      \
        for (int j = 0; j < 2; j++) {                                          \
            const int idx4 = tid * 2 + j;                                      \
            const int cc  = idx4 >> 7;                                         \
            const int rem = idx4 & 127;                                        \
            const int r   = rem >> 3;                                          \
            const int cg  = rem & 7;                                           \
            thr[j] = *(const float4*)&thb[(size_t)((c0) + cc) * PP +           \
                                          (h0 + r) * WW + w0 + cg * 4];        \
        }                                                                      \
        _Pragma("unroll")                                                      \
        for (int j = 0; j < 4; j++) {                                          \
            const int t = tid + j * 256;                                       \
            if (t < PH_F4) {                                                   \
                const int cc  = t / 240;                                       \
                const int rem = t - cc * 240;                                  \
                const int r   = rem / 10;                                      \
                const int cg  = rem - r * 10;                                  \
                const int hh   = h0 - DD + r;                                  \
                const int gcol = w0 - DD + cg * 4;                             \
                float4 v = make_float4(0.f, 0.f, 0.f, 0.f);                    \
                if (hh >= 0 && hh < HH && gcol >= 0 && gcol < WW)              \
                    v = *(const float4*)&phb[(size_t)((c0) + cc) * PP +        \
                                             hh * WW + gcol];                  \
                phr[j] = v;                                                    \
            }                                                                  \
        }                                                                      \
    }

    CORR_LOAD(ch0);

    const int nch = CPB / CCH;   // 64 chunks
    for (int c = 0; c < nch; c++) {
#pragma unroll
        for (int j = 0; j < 2; j++) ((float4*)th_s)[tid * 2 + j] = thr[j];
#pragma unroll
        for (int j = 0; j < 4; j++) {
            const int t = tid + j * 256;
            if (t < PH_F4) ((float4*)ph_s)[t] = phr[j];
        }
        __syncthreads();

        if (c + 1 < nch) CORR_LOAD(ch0 + (c + 1) * CCH);

#pragma unroll
        for (int cc = 0; cc < CCH; cc++) {
            const float t0 = th_s[cc * (CTH2 * CTW) + (2 * ty)     * CTW + tx];
            const float t1 = th_s[cc * (CTH2 * CTW) + (2 * ty + 1) * CTW + tx];
            const float* pr = &ph_s[cc * (CWH * CWW)];
#pragma unroll
            for (int rr = 0; rr < 10; rr++) {
                const float* row = &pr[(2 * ty + rr) * CWW + tx];
#pragma unroll
                for (int dx = 0; dx < 9; dx++) {
                    const float v = row[dx];
                    if (rr < 9) accA[rr * 9 + dx] += t0 * v;
                    if (rr >= 1) accB[(rr - 1) * 9 + dx] += t1 * v;
                }
            }
        }
        __syncthreads();
    }
#undef CORR_LOAD

    const int pixA = (h0 + 2 * ty) * WW + (w0 + tx);
    float* bp = pwpart + ((size_t)(ci * NB + b) * QQ) * PP;
#pragma unroll
    for (int q = 0; q < QQ; q++) {
        bp[(size_t)q * PP + pixA]      = accA[q];
        bp[(size_t)q * PP + pixA + WW] = accB[q];
    }
}

// ---------------------------------------------------------------------------
// Softmax over Q (sums the 2 channel-split partials, applies scale)
// ---------------------------------------------------------------------------
__global__ void __launch_bounds__(128)
softmax_kernel(const float* __restrict__ part, float* __restrict__ pw)
{
    const int t = blockIdx.x * 128 + threadIdx.x;
    const int b = t / PP;
    const int pix = t - b * PP;
    const size_t qp = (size_t)QQ * PP;
    const float scale = 256.0f / sqrtf((float)WW) / (float)CINT;

    float v[QQ];
    float m = -1e30f;
#pragma unroll
    for (int q = 0; q < QQ; q++) {
        const size_t off = (size_t)q * PP + pix;
        float s = part[(size_t)(0 * NB + b) * qp + off]
                + part[(size_t)(1 * NB + b) * qp + off];
        v[q] = s * scale;
        m = fmaxf(m, v[q]);
    }
    float s = 0.f;
#pragma unroll
    for (int q = 0; q < QQ; q++) { v[q] = __expf(v[q] - m); s += v[q]; }
    const float inv = 1.0f / s;
    float* pwb = pw + (size_t)b * qp + pix;
#pragma unroll
    for (int q = 0; q < QQ; q++) pwb[(size_t)q * PP] = v[q] * inv;
}

// ---------------------------------------------------------------------------
// Assemble, 2-pixel y-blocking + register-prefetch pipeline (CCH=4).
// ASPLIT=4: 128 channels per block, 32 chunks; halves pw re-read traffic.
// ---------------------------------------------------------------------------
__global__ void __launch_bounds__(256, 1)
assemble_kernel(const float* __restrict__ pw,
                const float* __restrict__ g,
                __nv_bfloat16* __restrict__ y)
{
    __shared__ __align__(16) float gs[CCH * CWH * CWW];   // 15 KB

    const int z  = blockIdx.z;
    const int b  = z >> 2;
    const int c0base = (z & 3) * (CINT / ASPLIT); // 128 channels
    const int w0 = blockIdx.x * CTW;
    const int h0 = blockIdx.y * CTH2;
    const int tid = threadIdx.x;
    const int tx = tid & 31;
    const int ty = tid >> 5;

    const float* gb  = g  + (size_t)b * CINT * PP;
    const float* pwb = pw + (size_t)b * QQ * PP;
    __nv_bfloat16* yb = y + (size_t)b * CINT * PP;

    const int pixA = (h0 + 2 * ty) * WW + (w0 + tx);
    const int pixB = pixA + WW;

    float rpwA[QQ], rpwB[QQ];
#pragma unroll
    for (int q = 0; q < QQ; q++) {
        rpwA[q] = pwb[(size_t)q * PP + pixA];
        rpwB[q] = pwb[(size_t)q * PP + pixB];
    }

    float4 gr4[4];

#define ASM_LOAD(c0)                                                           \
    {                                                                          \
        _Pragma("unroll")                                                      \
        for (int j = 0; j < 4; j++) {                                          \
            const int t = tid + j * 256;                                       \
            if (t < PH_F4) {                                                   \
                const int cc  = t / 240;                                       \
                const int rem = t - cc * 240;                                  \
                const int r   = rem / 10;                                      \
                const int cg  = rem - r * 10;                                  \
                const int hh   = h0 - DD + r;                                  \
                const int gcol = w0 - DD + cg * 4;                             \
                float4 v = make_float4(0.f, 0.f, 0.f, 0.f);                    \
                if (hh >= 0 && hh < HH && gcol >= 0 && gcol < WW)              \
                    v = *(const float4*)&gb[(size_t)((c0) + cc) * PP +         \
                                            hh * WW + gcol];                   \
                gr4[j] = v;                                                    \
            }                                                                  \
        }                                                                      \
    }

    ASM_LOAD(c0base);

    const int nch = (CINT / ASPLIT) / CCH;   // 32 chunks
    for (int c = 0; c < nch; c++) {
#pragma unroll
        for (int j = 0; j < 4; j++) {
            const int t = tid + j * 256;
            if (t < PH_F4) ((float4*)gs)[t] = gr4[j];
        }
        __syncthreads();

        if (c + 1 < nch) ASM_LOAD(c0base + (c + 1) * CCH);

        const int c0 = c0base + c * CCH;
#pragma unroll
        for (int cc = 0; cc < CCH; cc++) {
            const float* grp = &gs[cc * (CWH * CWW)];
            float aA = 0.f, aB = 0.f;
#pragma unroll
            for (int rr = 0; rr < 10; rr++) {
                const float* row = &grp[(2 * ty + rr) * CWW + tx];
#pragma unroll
                for (int dx = 0; dx < 9; dx++) {
                    const float v = row[dx];
                    if (rr < 9) aA += rpwA[rr * 9 + dx] * v;
                    if (rr >= 1) aB += rpwB[(rr - 1) * 9 + dx] * v;
                }
            }
            yb[(size_t)(c0 + cc) * PP + pixA] = __float2bfloat16(aA);
            yb[(size_t)(c0 + cc) * PP + pixB] = __float2bfloat16(aB);
        }
        __syncthreads();
    }
#undef ASM_LOAD
}

// ---------------------------------------------------------------------------
// Launch
// ---------------------------------------------------------------------------
extern "C" void kernel_launch(void* const* d_in, const int* in_sizes, int n_in,
                              void* d_out, int out_size)
{
    (void)in_sizes; (void)n_in; (void)out_size;

    const float* x       = (const float*)d_in[0];
    const float* x_ref   = (const float*)d_in[1];
    const float* w_g     = (const float*)d_in[2];
    const float* b_g     = (const float*)d_in[3];
    const float* w_theta = (const float*)d_in[4];
    const float* b_theta = (const float*)d_in[5];
    const float* w_phi   = (const float*)d_in[6];
    const float* b_phi   = (const float*)d_in[7];
    const float* w_out   = (const float*)d_in[8];
    const float* b_out   = (const float*)d_in[9];
    float* out = (float*)d_out;

    __nv_bfloat16 *xb, *xrefb, *wb, *yb;
    float *theta, *gbuf, *phi, *pwpart, *pw;
    cudaGetSymbolAddress((void**)&xb,     g_xb);
    cudaGetSymbolAddress((void**)&xrefb,  g_xrefb);
    cudaGetSymbolAddress((void**)&wb,     g_wb);
    cudaGetSymbolAddress((void**)&theta,  g_theta);
    cudaGetSymbolAddress((void**)&gbuf,   g_g);
    cudaGetSymbolAddress((void**)&phi,    g_phi);
    cudaGetSymbolAddress((void**)&pwpart, g_pwpart);
    cudaGetSymbolAddress((void**)&pw,     g_pw);
    cudaGetSymbolAddress((void**)&yb,     g_yb);

    cudaFuncSetAttribute(bgemm_kernel<false>, cudaFuncAttributeMaxDynamicSharedMemorySize, GEMM_SMEM);
    cudaFuncSetAttribute(bgemm_kernel<true>,  cudaFuncAttributeMaxDynamicSharedMemorySize, GEMM_SMEM);

    const int WSZ = CINT * CIN;
    __nv_bfloat16* wtb = wb + 0 * WSZ;
    __nv_bfloat16* wgb = wb + 1 * WSZ;
    __nv_bfloat16* wpb = wb + 2 * WSZ;
    __nv_bfloat16* wob = wb + 3 * WSZ;

    // conversions (2 launches)
    const int nx = NB * CIN * PP;
    dim3 cxg(nx / (256 * 8), 1, 2);
    convx_kernel<<<cxg, 256>>>(x, x_ref, xb, xrefb);
    dim3 cwg(WSZ / (256 * 8), 1, 4);
    convw_kernel<<<cwg, 256>>>(w_theta, w_g, w_phi, w_out, wb);

    // 1x1 convs (tensor-core GEMMs, BK=32, 3-stage pipeline)
    dim3 blk(256);
    dim3 gg1(PP / 128, CINT / 128, NB);     // (72, 4, 4)
    bgemm_kernel<false><<<gg1, blk, GEMM_SMEM>>>(wtb, xb,    b_theta, nullptr, theta, CINT, CIN, PP);
    bgemm_kernel<false><<<gg1, blk, GEMM_SMEM>>>(wgb, xrefb, b_g,     nullptr, gbuf,  CINT, CIN, PP);
    bgemm_kernel<false><<<gg1, blk, GEMM_SMEM>>>(wpb, xrefb, b_phi,   nullptr, phi,   CINT, CIN, PP);

    // correlation partials + softmax
    dim3 cg(WW / CTW, HH / CTH2, NB * CSPLIT);   // (3, 6, 8) = 144 blocks
    corr_kernel<<<cg, blk>>>(theta, phi, pwpart);
    softmax_kernel<<<(NB * PP) / 128, 128>>>(pwpart, pw);

    // assemble (bf16 output)
    dim3 ag(WW / CTW, HH / CTH2, NB * ASPLIT);   // (3, 6, 16) = 288 blocks
    assemble_kernel<<<ag, blk>>>(pw, gbuf, yb);

    // final conv + residual
    dim3 gg2(PP / 128, CIN / 128, NB);           // (72, 8, 4)
    bgemm_kernel<true><<<gg2, blk, GEMM_SMEM>>>(wob, yb, b_out, x, out, CIN, CINT, PP);
}

// round 17
// speedup vs baseline: 1.5621x; 1.0500x over previous
#include <cuda_runtime.h>
#include <cuda_bf16.h>
#include <math.h>
#include <stdint.h>

// Problem constants
#define NB    4
#define CIN   1024
#define CINT  512
#define HH    96
#define WW    96
#define PP    (HH * WW)      // 9216
#define DD    4
#define QQ    81
#define CSPLIT 2             // corr channel split
#define ASPLIT 4             // assemble channel split

// ---------------------------------------------------------------------------
// Scratch (device globals; no allocation allowed)
// ---------------------------------------------------------------------------
__device__ __align__(128) __nv_bfloat16 g_xb   [NB * CIN  * PP];
__device__ __align__(128) __nv_bfloat16 g_xrefb[NB * CIN  * PP];
__device__ __align__(128) __nv_bfloat16 g_wb   [4 * CINT * CIN];   // theta,g,phi,out
__device__ __align__(128) float g_theta [NB * CINT * PP];
__device__ __align__(128) float g_g     [NB * CINT * PP];
__device__ __align__(128) float g_phi   [NB * CINT * PP];
__device__ __align__(128) float g_pwpart[CSPLIT * NB * QQ * PP];
__device__ __align__(128) float g_pw    [NB * QQ * PP];
__device__ __align__(128) __nv_bfloat16 g_yb   [NB * CINT * PP];

// ---------------------------------------------------------------------------
// Helpers (legacy path: cp.async + ldmatrix + mma.sync; no tcgen05 — the
// toolchain targets sm_103 without the 'a' feature set)
// ---------------------------------------------------------------------------
__device__ __forceinline__ uint32_t sptr(const void* p) {
    return (uint32_t)__cvta_generic_to_shared(p);
}
__device__ __forceinline__ void cp16(uint32_t dst, const void* src) {
    asm volatile("cp.async.cg.shared.global [%0], [%1], 16;" :: "r"(dst), "l"(src));
}
__device__ __forceinline__ void cp_commit() {
    asm volatile("cp.async.commit_group;");
}
__device__ __forceinline__ void cp_wait0() {
    asm volatile("cp.async.wait_group 0;");
}
__device__ __forceinline__ void cp_wait1() {
    asm volatile("cp.async.wait_group 1;");
}
__device__ __forceinline__ void ldsmx4(uint32_t* r, uint32_t addr) {
    asm volatile("ldmatrix.sync.aligned.m8n8.x4.shared.b16 {%0,%1,%2,%3}, [%4];"
                 : "=r"(r[0]), "=r"(r[1]), "=r"(r[2]), "=r"(r[3]) : "r"(addr));
}
__device__ __forceinline__ void ldsmx4t(uint32_t* r, uint32_t addr) {
    asm volatile("ldmatrix.sync.aligned.m8n8.x4.trans.shared.b16 {%0,%1,%2,%3}, [%4];"
                 : "=r"(r[0]), "=r"(r[1]), "=r"(r[2]), "=r"(r[3]) : "r"(addr));
}
__device__ __forceinline__ void mma16816(float* c, const uint32_t* a, const uint32_t* b) {
    asm volatile("mma.sync.aligned.m16n8k16.row.col.f32.bf16.bf16.f32 "
                 "{%0,%1,%2,%3}, {%4,%5,%6,%7}, {%8,%9}, {%0,%1,%2,%3};"
                 : "+f"(c[0]), "+f"(c[1]), "+f"(c[2]), "+f"(c[3])
                 : "r"(a[0]), "r"(a[1]), "r"(a[2]), "r"(a[3]), "r"(b[0]), "r"(b[1]));
}

// ---------------------------------------------------------------------------
// Merged conversions: activations (z: 0=x, 1=x_ref) and weights (z: 0..3)
// ---------------------------------------------------------------------------
__global__ void __launch_bounds__(256)
convx_kernel(const float* __restrict__ x, const float* __restrict__ xref,
             __nv_bfloat16* __restrict__ xb, __nv_bfloat16* __restrict__ xrefb)
{
    const float* in = blockIdx.z ? xref : x;
    __nv_bfloat16* out = blockIdx.z ? xrefb : xb;
    int i = (blockIdx.x * 256 + threadIdx.x) * 8;
    float4 v0 = *(const float4*)(in + i);
    float4 v1 = *(const float4*)(in + i + 4);
    __nv_bfloat162 o[4];
    o[0] = __floats2bfloat162_rn(v0.x, v0.y);
    o[1] = __floats2bfloat162_rn(v0.z, v0.w);
    o[2] = __floats2bfloat162_rn(v1.x, v1.y);
    o[3] = __floats2bfloat162_rn(v1.z, v1.w);
    *(uint4*)(out + i) = *(const uint4*)o;
}

__global__ void __launch_bounds__(256)
convw_kernel(const float* __restrict__ w0, const float* __restrict__ w1,
             const float* __restrict__ w2, const float* __restrict__ w3,
             __nv_bfloat16* __restrict__ out)
{
    const int z = blockIdx.z;
    const float* in = (z == 0) ? w0 : (z == 1) ? w1 : (z == 2) ? w2 : w3;
    __nv_bfloat16* o = out + (size_t)z * (CINT * CIN);
    int i = (blockIdx.x * 256 + threadIdx.x) * 8;
    float4 v0 = *(const float4*)(in + i);
    float4 v1 = *(const float4*)(in + i + 4);
    __nv_bfloat162 p[4];
    p[0] = __floats2bfloat162_rn(v0.x, v0.y);
    p[1] = __floats2bfloat162_rn(v0.z, v0.w);
    p[2] = __floats2bfloat162_rn(v1.x, v1.y);
    p[3] = __floats2bfloat162_rn(v1.z, v1.w);
    *(uint4*)(o + i) = *(const uint4*)p;
}

// ---------------------------------------------------------------------------
// bf16 tensor-core GEMM (mma.sync), BK=32, 3-stage cp.async pipeline, ONE
// barrier per k-tile. EXACT round-11 configuration (regs=128, 122us/launch).
// ---------------------------------------------------------------------------
#define AS_STRIDE 40
#define BS_STRIDE 136
#define AS_ELEMS (128 * AS_STRIDE)
#define BS_ELEMS (32 * BS_STRIDE)
#define AS_BYTES (AS_ELEMS * 2)
#define BS_BYTES (BS_ELEMS * 2)
#define GEMM_STAGES 3
#define GEMM_SMEM (GEMM_STAGES * (AS_BYTES + BS_BYTES))   // 56832

__global__ void __launch_bounds__(256)
bgemm_kernel(const __nv_bfloat16* __restrict__ W, const __nv_bfloat16* __restrict__ Z,
             const float* __restrict__ bias, const float* __restrict__ res,
             float* __restrict__ O, int M, int K, int P)
{
    extern __shared__ __align__(16) char dsm[];

    const int b  = blockIdx.z;
    const __nv_bfloat16* Zb = Z + (size_t)b * K * P;
    float*       Ob = O + (size_t)b * M * P;
    const float* Rb = res ? res + (size_t)b * M * P : nullptr;

    const int m0 = blockIdx.y * 128;
    const int n0 = blockIdx.x * 128;
    const int tid  = threadIdx.x;
    const int lane = tid & 31;
    const int wid  = tid >> 5;
    const int wm = wid & 1;
    const int wn = wid >> 1;

    const uint32_t smem0 = sptr(dsm);
    const uint32_t bbase0 = smem0 + GEMM_STAGES * AS_BYTES;

    const int a_r = tid >> 2;
    const int a_c = tid & 3;
    const int b_r = tid >> 4;
    const int b_c = tid & 15;

    float acc[4][4][4];
#pragma unroll
    for (int mt = 0; mt < 4; mt++)
#pragma unroll
        for (int nt = 0; nt < 4; nt++)
#pragma unroll
            for (int i = 0; i < 4; i++) acc[mt][nt][i] = 0.f;

    const int nk = K >> 5;

#pragma unroll
    for (int pt = 0; pt < 2; pt++) {
        const uint32_t as = smem0 + pt * AS_BYTES;
        const uint32_t bs = bbase0 + pt * BS_BYTES;
        const int k0 = pt * 32;
        cp16(as + (uint32_t)((a_r)      * AS_STRIDE + a_c * 8) * 2, W  + (size_t)(m0 + a_r)      * K + k0 + a_c * 8);
        cp16(as + (uint32_t)((a_r + 64) * AS_STRIDE + a_c * 8) * 2, W  + (size_t)(m0 + a_r + 64) * K + k0 + a_c * 8);
        cp16(bs + (uint32_t)((b_r)      * BS_STRIDE + b_c * 8) * 2, Zb + (size_t)(k0 + b_r)      * P + n0 + b_c * 8);
        cp16(bs + (uint32_t)((b_r + 16) * BS_STRIDE + b_c * 8) * 2, Zb + (size_t)(k0 + b_r + 16) * P + n0 + b_c * 8);
        cp_commit();
    }

    int s = 0;
    for (int kt = 0; kt < nk; kt++) {
        if (kt + 1 < nk) cp_wait1(); else cp_wait0();
        __syncthreads();

        if (kt + 2 < nk) {
            int sp = s + 2; if (sp >= GEMM_STAGES) sp -= GEMM_STAGES;
            const uint32_t as = smem0 + sp * AS_BYTES;
            const uint32_t bs = bbase0 + sp * BS_BYTES;
            const int k0 = (kt + 2) * 32;
            cp16(as + (uint32_t)((a_r)      * AS_STRIDE + a_c * 8) * 2, W  + (size_t)(m0 + a_r)      * K + k0 + a_c * 8);
            cp16(as + (uint32_t)((a_r + 64) * AS_STRIDE + a_c * 8) * 2, W  + (size_t)(m0 + a_r + 64) * K + k0 + a_c * 8);
            cp16(bs + (uint32_t)((b_r)      * BS_STRIDE + b_c * 8) * 2, Zb + (size_t)(k0 + b_r)      * P + n0 + b_c * 8);
            cp16(bs + (uint32_t)((b_r + 16) * BS_STRIDE + b_c * 8) * 2, Zb + (size_t)(k0 + b_r + 16) * P + n0 + b_c * 8);
            cp_commit();
        }

        const uint32_t as = smem0 + s * AS_BYTES;
        const uint32_t bs = bbase0 + s * BS_BYTES;

#pragma unroll
        for (int kk = 0; kk < 2; kk++) {
            const int k0 = kk * 16;
            uint32_t a[4][4];
            const uint32_t a_base = as + (uint32_t)(((wm * 64 + (lane & 15)) * AS_STRIDE) + k0 + (lane >> 4) * 8) * 2;
#pragma unroll
            for (int mt = 0; mt < 4; mt++)
                ldsmx4(a[mt], a_base + (uint32_t)(mt * 16 * AS_STRIDE) * 2);

            uint32_t bb[4][2];
            const uint32_t b_base = bs + (uint32_t)((k0 + (lane & 15)) * BS_STRIDE + wn * 32 + (lane >> 4) * 8) * 2;
            {
                uint32_t r[4];
                ldsmx4t(r, b_base);
                bb[0][0] = r[0]; bb[0][1] = r[1];
                bb[1][0] = r[2]; bb[1][1] = r[3];
                ldsmx4t(r, b_base + 16 * 2);
                bb[2][0] = r[0]; bb[2][1] = r[1];
                bb[3][0] = r[2]; bb[3][1] = r[3];
            }

#pragma unroll
            for (int mt = 0; mt < 4; mt++)
#pragma unroll
                for (int nt = 0; nt < 4; nt++)
                    mma16816(acc[mt][nt], a[mt], bb[nt]);
        }
        if (++s == GEMM_STAGES) s = 0;
    }

#pragma unroll
    for (int mt = 0; mt < 4; mt++) {
        const int r0 = m0 + wm * 64 + mt * 16 + (lane >> 2);
        const int r1 = r0 + 8;
        const float bv0 = bias[r0];
        const float bv1 = bias[r1];
#pragma unroll
        for (int nt = 0; nt < 4; nt++) {
            const int col = n0 + wn * 32 + nt * 8 + (lane & 3) * 2;
            float2 v0 = make_float2(acc[mt][nt][0] + bv0, acc[mt][nt][1] + bv0);
            float2 v1 = make_float2(acc[mt][nt][2] + bv1, acc[mt][nt][3] + bv1);
            if (Rb) {
                float2 t0 = *(const float2*)&Rb[(size_t)r0 * P + col];
                float2 t1 = *(const float2*)&Rb[(size_t)r1 * P + col];
                v0.x += t0.x; v0.y += t0.y;
                v1.x += t1.x; v1.y += t1.y;
            }
            *(float2*)&Ob[(size_t)r0 * P + col] = v0;
            *(float2*)&Ob[(size_t)r1 * P + col] = v1;
        }
    }
}

// ---------------------------------------------------------------------------
// Correlation, 2-pixel y-blocking + register-prefetch pipeline (CCH=4).
// (round-11 proven version, unchanged)
// ---------------------------------------------------------------------------
#define CTW 32
#define CTH2 16
#define CWW (CTW + 2 * DD)    // 40
#define CWH (CTH2 + 2 * DD)   // 24
#define CCH 4
#define CPB (CINT / CSPLIT)   // 256
#define TH_F4 ((CCH * CTH2 * CTW) / 4)   // 512 float4
#define PH_F4 ((CCH * CWH * CWW) / 4)    // 960 float4

__global__ void __launch_bounds__(256, 1)
corr_kernel(const float* __restrict__ theta,
            const float* __restrict__ phi,
            float* __restrict__ pwpart)
{
    __shared__ __align__(16) float th_s[CCH * CTH2 * CTW];   // 8 KB
    __shared__ __align__(16) float ph_s[CCH * CWH * CWW];    // 15 KB

    const int z  = blockIdx.z;
    const int b  = z >> 1;
    const int ci = z & 1;
    const int ch0 = ci * CPB;
    const int w0 = blockIdx.x * CTW;
    const int h0 = blockIdx.y * CTH2;
    const int tid = threadIdx.x;
    const int tx = tid & 31;
    const int ty = tid >> 5;          // 0..7 -> pixel rows 2ty, 2ty+1

    const float* thb = theta + (size_t)b * CINT * PP;
    const float* phb = phi   + (size_t)b * CINT * PP;

    float accA[QQ], accB[QQ];
#pragma unroll
    for (int q = 0; q < QQ; q++) { accA[q] = 0.f; accB[q] = 0.f; }

    float4 thr[2];
    float4 phr[4];

#define CORR_LOAD(c0)                                                          \
    {                                                                          \
        _Pragma("unroll")                                                      \
        for (int j = 0; j < 2; j++) {                                          \
            const int idx4 = tid * 2 + j;                                      \
            const int cc  = idx4 >> 7;                                         \
            const int rem = idx4 & 127;                                        \
            const int r   = rem >> 3;                                          \
            const int cg  = rem & 7;                                           \
            thr[j] = *(const float4*)&thb[(size_t)((c0) + cc) * PP +           \
                                          (h0 + r) * WW + w0 + cg * 4];        \
        }                                                                      \
        _Pragma("unroll")                                                      \
        for (int j = 0; j < 4; j++) {                                          \
            const int t = tid + j * 256;                                       \
            if (t < PH_F4) {                                                   \
                const int cc  = t / 240;                                       \
                const int rem = t - cc * 240;                                  \
                const int r   = rem / 10;                                      \
                const int cg  = rem - r * 10;                                  \
                const int hh   = h0 - DD + r;                                  \
                const int gcol = w0 - DD + cg * 4;                             \
                float4 v = make_float4(0.f, 0.f, 0.f, 0.f);                    \
                if (hh >= 0 && hh < HH && gcol >= 0 && gcol < WW)              \
                    v = *(const float4*)&phb[(size_t)((c0) + cc) * PP +        \
                                             hh * WW + gcol];                  \
                phr[j] = v;                                                    \
            }                                                                  \
        }                                                                      \
    }

    CORR_LOAD(ch0);

    const int nch = CPB / CCH;   // 64 chunks
    for (int c = 0; c < nch; c++) {
#pragma unroll
        for (int j = 0; j < 2; j++) ((float4*)th_s)[tid * 2 + j] = thr[j];
#pragma unroll
        for (int j = 0; j < 4; j++) {
            const int t = tid + j * 256;
            if (t < PH_F4) ((float4*)ph_s)[t] = phr[j];
        }
        __syncthreads();

        if (c + 1 < nch) CORR_LOAD(ch0 + (c + 1) * CCH);

#pragma unroll
        for (int cc = 0; cc < CCH; cc++) {
            const float t0 = th_s[cc * (CTH2 * CTW) + (2 * ty)     * CTW + tx];
            const float t1 = th_s[cc * (CTH2 * CTW) + (2 * ty + 1) * CTW + tx];
            const float* pr = &ph_s[cc * (CWH * CWW)];
#pragma unroll
            for (int rr = 0; rr < 10; rr++) {
                const float* row = &pr[(2 * ty + rr) * CWW + tx];
#pragma unroll
                for (int dx = 0; dx < 9; dx++) {
                    const float v = row[dx];
                    if (rr < 9) accA[rr * 9 + dx] += t0 * v;
                    if (rr >= 1) accB[(rr - 1) * 9 + dx] += t1 * v;
                }
            }
        }
        __syncthreads();
    }
#undef CORR_LOAD

    const int pixA = (h0 + 2 * ty) * WW + (w0 + tx);
    float* bp = pwpart + ((size_t)(ci * NB + b) * QQ) * PP;
#pragma unroll
    for (int q = 0; q < QQ; q++) {
        bp[(size_t)q * PP + pixA]      = accA[q];
        bp[(size_t)q * PP + pixA + WW] = accB[q];
    }
}

// ---------------------------------------------------------------------------
// Softmax over Q (sums the 2 channel-split partials, applies scale)
// ---------------------------------------------------------------------------
__global__ void __launch_bounds__(128)
softmax_kernel(const float* __restrict__ part, float* __restrict__ pw)
{
    const int t = blockIdx.x * 128 + threadIdx.x;
    const int b = t / PP;
    const int pix = t - b * PP;
    const size_t qp = (size_t)QQ * PP;
    const float scale = 256.0f / sqrtf((float)WW) / (float)CINT;

    float v[QQ];
    float m = -1e30f;
#pragma unroll
    for (int q = 0; q < QQ; q++) {
        const size_t off = (size_t)q * PP + pix;
        float s = part[(size_t)(0 * NB + b) * qp + off]
                + part[(size_t)(1 * NB + b) * qp + off];
        v[q] = s * scale;
        m = fmaxf(m, v[q]);
    }
    float s = 0.f;
#pragma unroll
    for (int q = 0; q < QQ; q++) { v[q] = __expf(v[q] - m); s += v[q]; }
    const float inv = 1.0f / s;
    float* pwb = pw + (size_t)b * qp + pix;
#pragma unroll
    for (int q = 0; q < QQ; q++) pwb[(size_t)q * PP] = v[q] * inv;
}

// ---------------------------------------------------------------------------
// Assemble, 2-pixel y-blocking + register-prefetch pipeline (CCH=4).
// ASPLIT=4: 128 channels per block, 32 chunks; halves pw re-read traffic.
// ---------------------------------------------------------------------------
__global__ void __launch_bounds__(256, 1)
assemble_kernel(const float* __restrict__ pw,
                const float* __restrict__ g,
                __nv_bfloat16* __restrict__ y)
{
    __shared__ __align__(16) float gs[CCH * CWH * CWW];   // 15 KB

    const int z  = blockIdx.z;
    const int b  = z >> 2;
    const int c0base = (z & 3) * (CINT / ASPLIT); // 128 channels
    const int w0 = blockIdx.x * CTW;
    const int h0 = blockIdx.y * CTH2;
    const int tid = threadIdx.x;
    const int tx = tid & 31;
    const int ty = tid >> 5;

    const float* gb  = g  + (size_t)b * CINT * PP;
    const float* pwb = pw + (size_t)b * QQ * PP;
    __nv_bfloat16* yb = y + (size_t)b * CINT * PP;

    const int pixA = (h0 + 2 * ty) * WW + (w0 + tx);
    const int pixB = pixA + WW;

    float rpwA[QQ], rpwB[QQ];
#pragma unroll
    for (int q = 0; q < QQ; q++) {
        rpwA[q] = pwb[(size_t)q * PP + pixA];
        rpwB[q] = pwb[(size_t)q * PP + pixB];
    }

    float4 gr4[4];

#define ASM_LOAD(c0)                                                           \
    {                                                                          \
        _Pragma("unroll")                                                      \
        for (int j = 0; j < 4; j++) {                                          \
            const int t = tid + j * 256;                                       \
            if (t < PH_F4) {                                                   \
                const int cc  = t / 240;                                       \
                const int rem = t - cc * 240;                                  \
                const int r   = rem / 10;                                      \
                const int cg  = rem - r * 10;                                  \
                const int hh   = h0 - DD + r;                                  \
                const int gcol = w0 - DD + cg * 4;                             \
                float4 v = make_float4(0.f, 0.f, 0.f, 0.f);                    \
                if (hh >= 0 && hh < HH && gcol >= 0 && gcol < WW)              \
                    v = *(const float4*)&gb[(size_t)((c0) + cc) * PP +         \
                                            hh * WW + gcol];                   \
                gr4[j] = v;                                                    \
            }                                                                  \
        }                                                                      \
    }

    ASM_LOAD(c0base);

    const int nch = (CINT / ASPLIT) / CCH;   // 32 chunks
    for (int c = 0; c < nch; c++) {
#pragma unroll
        for (int j = 0; j < 4; j++) {
            const int t = tid + j * 256;
            if (t < PH_F4) ((float4*)gs)[t] = gr4[j];
        }
        __syncthreads();

        if (c + 1 < nch) ASM_LOAD(c0base + (c + 1) * CCH);

        const int c0 = c0base + c * CCH;
#pragma unroll
        for (int cc = 0; cc < CCH; cc++) {
            const float* grp = &gs[cc * (CWH * CWW)];
            float aA = 0.f, aB = 0.f;
#pragma unroll
            for (int rr = 0; rr < 10; rr++) {
                const float* row = &grp[(2 * ty + rr) * CWW + tx];
#pragma unroll
                for (int dx = 0; dx < 9; dx++) {
                    const float v = row[dx];
                    if (rr < 9) aA += rpwA[rr * 9 + dx] * v;
                    if (rr >= 1) aB += rpwB[(rr - 1) * 9 + dx] * v;
                }
            }
            yb[(size_t)(c0 + cc) * PP + pixA] = __float2bfloat16(aA);
            yb[(size_t)(c0 + cc) * PP + pixB] = __float2bfloat16(aB);
        }
        __syncthreads();
    }
#undef ASM_LOAD
}

// ---------------------------------------------------------------------------
// Launch
// ---------------------------------------------------------------------------
extern "C" void kernel_launch(void* const* d_in, const int* in_sizes, int n_in,
                              void* d_out, int out_size)
{
    (void)in_sizes; (void)n_in; (void)out_size;

    const float* x       = (const float*)d_in[0];
    const float* x_ref   = (const float*)d_in[1];
    const float* w_g     = (const float*)d_in[2];
    const float* b_g     = (const float*)d_in[3];
    const float* w_theta = (const float*)d_in[4];
    const float* b_theta = (const float*)d_in[5];
    const float* w_phi   = (const float*)d_in[6];
    const float* b_phi   = (const float*)d_in[7];
    const float* w_out   = (const float*)d_in[8];
    const float* b_out   = (const float*)d_in[9];
    float* out = (float*)d_out;

    __nv_bfloat16 *xb, *xrefb, *wb, *yb;
    float *theta, *gbuf, *phi, *pwpart, *pw;
    cudaGetSymbolAddress((void**)&xb,     g_xb);
    cudaGetSymbolAddress((void**)&xrefb,  g_xrefb);
    cudaGetSymbolAddress((void**)&wb,     g_wb);
    cudaGetSymbolAddress((void**)&theta,  g_theta);
    cudaGetSymbolAddress((void**)&gbuf,   g_g);
    cudaGetSymbolAddress((void**)&phi,    g_phi);
    cudaGetSymbolAddress((void**)&pwpart, g_pwpart);
    cudaGetSymbolAddress((void**)&pw,     g_pw);
    cudaGetSymbolAddress((void**)&yb,     g_yb);

    cudaFuncSetAttribute(bgemm_kernel, cudaFuncAttributeMaxDynamicSharedMemorySize, GEMM_SMEM);

    const int WSZ = CINT * CIN;
    __nv_bfloat16* wtb = wb + 0 * WSZ;
    __nv_bfloat16* wgb = wb + 1 * WSZ;
    __nv_bfloat16* wpb = wb + 2 * WSZ;
    __nv_bfloat16* wob = wb + 3 * WSZ;

    // conversions (2 launches)
    const int nx = NB * CIN * PP;
    dim3 cxg(nx / (256 * 8), 1, 2);
    convx_kernel<<<cxg, 256>>>(x, x_ref, xb, xrefb);
    dim3 cwg(WSZ / (256 * 8), 1, 4);
    convw_kernel<<<cwg, 256>>>(w_theta, w_g, w_phi, w_out, wb);

    // 1x1 convs (tensor-core GEMMs, BK=32, 3-stage pipeline)
    dim3 blk(256);
    dim3 gg1(PP / 128, CINT / 128, NB);     // (72, 4, 4)
    bgemm_kernel<<<gg1, blk, GEMM_SMEM>>>(wtb, xb,    b_theta, nullptr, theta, CINT, CIN, PP);
    bgemm_kernel<<<gg1, blk, GEMM_SMEM>>>(wgb, xrefb, b_g,     nullptr, gbuf,  CINT, CIN, PP);
    bgemm_kernel<<<gg1, blk, GEMM_SMEM>>>(wpb, xrefb, b_phi,   nullptr, phi,   CINT, CIN, PP);

    // correlation partials + softmax
    dim3 cg(WW / CTW, HH / CTH2, NB * CSPLIT);   // (3, 6, 8) = 144 blocks
    corr_kernel<<<cg, blk>>>(theta, phi, pwpart);
    softmax_kernel<<<(NB * PP) / 128, 128>>>(pwpart, pw);

    // assemble (bf16 output)
    dim3 ag(WW / CTW, HH / CTH2, NB * ASPLIT);   // (3, 6, 16) = 288 blocks
    assemble_kernel<<<ag, blk>>>(pw, gbuf, yb);

    // final conv + residual
    dim3 gg2(PP / 128, CIN / 128, NB);           // (72, 8, 4)
    bgemm_kernel<<<gg2, blk, GEMM_SMEM>>>(wob, yb, b_out, x, out, CIN, CINT, PP);
}